// round 6
// baseline (speedup 1.0000x reference)
#include <cuda_runtime.h>
#include <math.h>

#define BN_EPS 1e-5f

// ---------------------------------------------------------------------------
// Static device scratch
// ---------------------------------------------------------------------------
__device__ float g_bufA[131072 * 128];
__device__ float g_bufB[131072 * 128];
__device__ float g_f1[8 * 512 * 128];
__device__ float g_f2[8 * 128 * 256];
__device__ float g_sa3in[1024 * 259];
__device__ float g_gfeat[8 * 128];
__device__ float g_objfeat[8 * 1024];
__device__ float g_comb[8 * 1152];
__device__ float g_h0[8 * 512];
__device__ float g_h1[8 * 256];
__device__ float g_xyz1[8 * 512 * 3];
__device__ float g_xyz2[8 * 128 * 3];
__device__ int   g_fps1[8 * 512];
__device__ int   g_fps2[8 * 128];
__device__ int   g_bq1[8 * 512 * 32];
__device__ int   g_bq2[8 * 128 * 64];
__device__ float g_bnsum[4096];
__device__ float g_bnsq[4096];

// ---------------------------------------------------------------------------
// Tiled GEMM:  Y[M,N] = f(X)[M,K] * W[N,K]^T
//  BM=128, BN_ in {64,128}, BK=16, 256 threads, microtile 8 x (BN_/16).
//  Double-buffered smem with register staging of global loads.
//  Input modes:
//    gather (gIdx != null): A[g][c] built from point gather (ball-query fusion)
//    bn     (inSum != null): A = relu((X - mean)*inv), mean/inv from raw sums
//    plain  otherwise
//  Epilogue: optional per-column sum/sumsq accumulation (for next layer's BN).
// ---------------------------------------------------------------------------
template<int BN_>
__global__ __launch_bounds__(256) void gemm_tile_kernel(
    const float* __restrict__ X, const float* __restrict__ W,
    float* __restrict__ Y, int M, int N, int K,
    const float* __restrict__ inSum, const float* __restrict__ inSq, float invMin,
    float* __restrict__ outSum, float* __restrict__ outSq,
    const int* __restrict__ gIdx, const float* __restrict__ gPts,
    const float* __restrict__ gCtr, const float* __restrict__ gFeats,
    int gNpts, int gBShift, int gNsShift, int gCF, float gRad)
{
    constexpr int TN = BN_ / 16;
    __shared__ __align__(16) float As[2][16][132];
    __shared__ __align__(16) float Bs[2][16][BN_ + 4];
    __shared__ float sMean[512];
    __shared__ float sInv[512];
    __shared__ int   sPid[128];
    __shared__ float sSum[BN_];
    __shared__ float sSq[BN_];

    const int bm = blockIdx.y * 128;
    const int bn = blockIdx.x * BN_;
    const int t  = threadIdx.x;
    const int ty = t >> 4;
    const int tx = t & 15;

    const bool useBn = (inSum != nullptr);
    const bool useG  = (gIdx != nullptr);

    if (useBn) {
        for (int k = t; k < K; k += 256) {
            float m = inSum[k] * invMin;
            float var = fmaxf(inSq[k] * invMin - m * m, 0.f);
            sMean[k] = m;
            sInv[k] = 1.f / sqrtf(var + BN_EPS);
        }
    }
    if (useG && t < 128) {
        int g = bm + t;
        int pid = 0;
        if (g < M) pid = (g >> gBShift) * gNpts + gIdx[g];
        sPid[t] = pid;
    }
    if (useBn || useG) __syncthreads();

    float acc[8][TN];
#pragma unroll
    for (int i = 0; i < 8; i++)
#pragma unroll
        for (int j = 0; j < TN; j++) acc[i][j] = 0.f;

    float aReg[8];
    float bReg[TN];

    auto loadA = [&](int k0) {
#pragma unroll
        for (int i = 0; i < 8; i++) {
            int lin = i * 256 + t;
            int r = lin >> 4, c = lin & 15;
            int gm = bm + r, gk = k0 + c;
            float v = 0.f;
            if (gk < K && gm < M) {
                if (useG) {
                    int pid = sPid[r];
                    if (gk < 3) {
                        int cr = gm >> gNsShift;
                        v = __fdiv_rn(__fsub_rn(gPts[(size_t)pid * 3 + gk],
                                                gCtr[(size_t)cr * 3 + gk]), gRad);
                    } else {
                        v = gFeats[(size_t)pid * gCF + (gk - 3)];
                    }
                } else {
                    v = X[(size_t)gm * K + gk];
                    if (useBn) v = fmaxf(0.f, (v - sMean[gk]) * sInv[gk]);
                }
            }
            aReg[i] = v;
        }
    };
    auto loadB = [&](int k0) {
#pragma unroll
        for (int i = 0; i < TN; i++) {
            int lin = i * 256 + t;
            int r = lin >> 4, c = lin & 15;
            int gn = bn + r, gk = k0 + c;
            bReg[i] = (gk < K && gn < N) ? W[(size_t)gn * K + gk] : 0.f;
        }
    };
    auto storeS = [&](int buf) {
#pragma unroll
        for (int i = 0; i < 8; i++) {
            int lin = i * 256 + t;
            As[buf][lin & 15][lin >> 4] = aReg[i];
        }
#pragma unroll
        for (int i = 0; i < TN; i++) {
            int lin = i * 256 + t;
            Bs[buf][lin & 15][lin >> 4] = bReg[i];
        }
    };
    auto compute = [&](int buf) {
#pragma unroll
        for (int kk = 0; kk < 16; kk++) {
            float a[8], b[TN];
            float4 a0 = *reinterpret_cast<const float4*>(&As[buf][kk][ty * 8]);
            float4 a1 = *reinterpret_cast<const float4*>(&As[buf][kk][ty * 8 + 4]);
            a[0] = a0.x; a[1] = a0.y; a[2] = a0.z; a[3] = a0.w;
            a[4] = a1.x; a[5] = a1.y; a[6] = a1.z; a[7] = a1.w;
#pragma unroll
            for (int jj = 0; jj < TN / 4; jj++) {
                float4 bv = *reinterpret_cast<const float4*>(&Bs[buf][kk][tx * TN + jj * 4]);
                b[jj * 4 + 0] = bv.x; b[jj * 4 + 1] = bv.y;
                b[jj * 4 + 2] = bv.z; b[jj * 4 + 3] = bv.w;
            }
#pragma unroll
            for (int i = 0; i < 8; i++)
#pragma unroll
                for (int j = 0; j < TN; j++)
                    acc[i][j] = fmaf(a[i], b[j], acc[i][j]);
        }
    };

    const int nk = (K + 15) / 16;
    loadA(0); loadB(0);
    storeS(0);
    __syncthreads();
    for (int kt = 1; kt < nk; kt++) {
        loadA(kt * 16); loadB(kt * 16);
        compute((kt - 1) & 1);
        storeS(kt & 1);
        __syncthreads();
    }
    compute((nk - 1) & 1);

    // epilogue: store + optional per-column stats
    float colS[TN];
    float colQ[TN];
#pragma unroll
    for (int j = 0; j < TN; j++) { colS[j] = 0.f; colQ[j] = 0.f; }
#pragma unroll
    for (int i = 0; i < 8; i++) {
        int gm = bm + ty * 8 + i;
        if (gm >= M) continue;
#pragma unroll
        for (int j = 0; j < TN; j++) {
            int gn = bn + tx * TN + j;
            if (gn >= N) continue;
            float v = acc[i][j];
            Y[(size_t)gm * N + gn] = v;
            colS[j] += v;
            colQ[j] = fmaf(v, v, colQ[j]);
        }
    }

    if (outSum) {
#pragma unroll
        for (int j = 0; j < TN; j++) {
            colS[j] += __shfl_down_sync(0xffffffffu, colS[j], 16);
            colQ[j] += __shfl_down_sync(0xffffffffu, colQ[j], 16);
        }
        if (t < BN_) { sSum[t] = 0.f; sSq[t] = 0.f; }
        __syncthreads();
        if ((t & 31) < 16) {
#pragma unroll
            for (int j = 0; j < TN; j++) {
                atomicAdd(&sSum[tx * TN + j], colS[j]);
                atomicAdd(&sSq[tx * TN + j], colQ[j]);
            }
        }
        __syncthreads();
        if (t < BN_) {
            int gn = bn + t;
            if (gn < N) {
                atomicAdd(&outSum[gn], sSum[t]);
                atomicAdd(&outSq[gn], sSq[t]);
            }
        }
    }
}

// ---------------------------------------------------------------------------
// Small-M GEMM for the head (M <= 8): warp-per-column, X cached in smem.
// ---------------------------------------------------------------------------
__global__ __launch_bounds__(256) void gemm_small_kernel(
    const float* __restrict__ X, const float* __restrict__ W,
    const float* __restrict__ bias, float* __restrict__ Y,
    int M, int N, int K, int relu)
{
    __shared__ float sX[8 * 1152];
    for (int i = threadIdx.x; i < M * K; i += 256) sX[i] = X[i];
    __syncthreads();
    int warp = threadIdx.x >> 5, lane = threadIdx.x & 31;
    int n = blockIdx.x * 8 + warp;
    if (n >= N) return;
    float acc[8];
#pragma unroll
    for (int m = 0; m < 8; m++) acc[m] = 0.f;
    for (int k = lane; k < K; k += 32) {
        float wv = W[(size_t)n * K + k];
#pragma unroll
        for (int m = 0; m < 8; m++)
            acc[m] = fmaf(sX[m * K + k], wv, acc[m]);
    }
#pragma unroll
    for (int m = 0; m < 8; m++) {
#pragma unroll
        for (int o = 16; o > 0; o >>= 1)
            acc[m] += __shfl_down_sync(0xffffffffu, acc[m], o);
    }
    if (lane == 0) {
        for (int m = 0; m < M; m++) {
            float v = acc[m] + bias[n];
            if (relu) v = fmaxf(v, 0.f);
            Y[(size_t)m * N + n] = v;
        }
    }
}

// ---------------------------------------------------------------------------
// BN helpers
// ---------------------------------------------------------------------------
__global__ void bn_zero_kernel(float* s, float* q, int C)
{
    int i = blockIdx.x * blockDim.x + threadIdx.x;
    if (i < C) { s[i] = 0.f; q[i] = 0.f; }
}

// exact per-column BN for small M (head path), in place
__global__ void bn_col_kernel(float* __restrict__ X, int M, int C, int relu)
{
    int c = blockIdx.x * blockDim.x + threadIdx.x;
    if (c >= C) return;
    float s = 0.f, q = 0.f;
    for (int m = 0; m < M; m++) {
        float v = X[(size_t)m * C + c];
        s += v;
        q = fmaf(v, v, q);
    }
    float mean = s / (float)M;
    float var = fmaxf(q / (float)M - mean * mean, 0.f);
    float inv = 1.f / sqrtf(var + BN_EPS);
    for (int m = 0; m < M; m++) {
        float v = (X[(size_t)m * C + c] - mean) * inv;
        if (relu) v = fmaxf(v, 0.f);
        X[(size_t)m * C + c] = v;
    }
}

// ---------------------------------------------------------------------------
// Max pool over group axis + BN(from raw sums) + ReLU
// ---------------------------------------------------------------------------
__global__ void maxpool_bn_kernel(const float* __restrict__ X, float* __restrict__ Y,
                                  int R, int ns, int C,
                                  const float* __restrict__ gsum,
                                  const float* __restrict__ gsq, float invM)
{
    unsigned total = (unsigned)R * C;
    unsigned stride = gridDim.x * blockDim.x;
    for (unsigned e = blockIdx.x * blockDim.x + threadIdx.x; e < total; e += stride) {
        int r = e / C;
        int c = e % C;
        const float* p = X + ((size_t)r * ns) * C + c;
        float m = -3.402823466e38f;
        for (int j = 0; j < ns; j++) m = fmaxf(m, p[(size_t)j * C]);
        float mean = gsum[c] * invM;
        float var = fmaxf(gsq[c] * invM - mean * mean, 0.f);
        float inv = 1.f / sqrtf(var + BN_EPS);
        Y[e] = fmaxf(0.f, (m - mean) * inv);
    }
}

// ---------------------------------------------------------------------------
// FPS1: one block per batch, 512 threads, 40 pts/thread, xy in 160KB smem.
// 2 syncthreads per iteration, npoint-1 update rounds.
// ---------------------------------------------------------------------------
__global__ void __launch_bounds__(512) fps1_kernel(
    const float* __restrict__ xyz, int N, int npoint,
    int* __restrict__ idx_out, float* __restrict__ newxyz)
{
    extern __shared__ float2 sxy[];
    const int b = blockIdx.x;
    const int T = 512;
    const int t = threadIdx.x;
    const float* P = xyz + (size_t)b * N * 3;

    __shared__ float s_v[16];
    __shared__ int   s_i[16];
    __shared__ float s_far[3];

    for (int p = t; p < N; p += T)
        sxy[p] = make_float2(P[p * 3 + 0], P[p * 3 + 1]);

    float zreg[40];
    float dist[40];
#pragma unroll
    for (int k = 0; k < 40; k++) {
        int p = t + k * T;
        zreg[k] = (p < N) ? P[p * 3 + 2] : 0.f;
        dist[k] = 1e10f;
    }
    if (t == 0) {
        idx_out[b * npoint] = 0;
        float fx = P[0], fy = P[1], fz = P[2];
        newxyz[(size_t)b * npoint * 3 + 0] = fx;
        newxyz[(size_t)b * npoint * 3 + 1] = fy;
        newxyz[(size_t)b * npoint * 3 + 2] = fz;
        s_far[0] = fx; s_far[1] = fy; s_far[2] = fz;
    }
    __syncthreads();

    for (int it = 1; it < npoint; it++) {
        float fx = s_far[0], fy = s_far[1], fz = s_far[2];
        float best = -1.f;
        int bi = 0x7fffffff;
#pragma unroll
        for (int k = 0; k < 40; k++) {
            int p = t + k * T;
            if (p < N) {
                float2 xy = sxy[p];
                float dx = __fsub_rn(xy.x, fx);
                float dy = __fsub_rn(xy.y, fy);
                float dz = __fsub_rn(zreg[k], fz);
                float d = __fadd_rn(__fadd_rn(__fmul_rn(dx, dx), __fmul_rn(dy, dy)),
                                    __fmul_rn(dz, dz));
                float nd = fminf(dist[k], d);
                dist[k] = nd;
                if (nd > best) { best = nd; bi = p; }
            }
        }
#pragma unroll
        for (int o = 16; o > 0; o >>= 1) {
            float ov = __shfl_down_sync(0xffffffffu, best, o);
            int   oi = __shfl_down_sync(0xffffffffu, bi, o);
            if (ov > best || (ov == best && oi < bi)) { best = ov; bi = oi; }
        }
        if ((t & 31) == 0) { s_v[t >> 5] = best; s_i[t >> 5] = bi; }
        __syncthreads();
        if (t < 32) {
            best = (t < 16) ? s_v[t] : -1.f;
            bi   = (t < 16) ? s_i[t] : 0x7fffffff;
#pragma unroll
            for (int o = 8; o > 0; o >>= 1) {
                float ov = __shfl_down_sync(0xffffffffu, best, o);
                int   oi = __shfl_down_sync(0xffffffffu, bi, o);
                if (ov > best || (ov == best && oi < bi)) { best = ov; bi = oi; }
            }
            if (t == 0) {
                float2 fxy = sxy[bi];
                float fz2 = P[bi * 3 + 2];
                idx_out[b * npoint + it] = bi;
                newxyz[((size_t)b * npoint + it) * 3 + 0] = fxy.x;
                newxyz[((size_t)b * npoint + it) * 3 + 1] = fxy.y;
                newxyz[((size_t)b * npoint + it) * 3 + 2] = fz2;
                s_far[0] = fxy.x; s_far[1] = fxy.y; s_far[2] = fz2;
            }
        }
        __syncthreads();
    }
}

// ---------------------------------------------------------------------------
// FPS2: one warp per batch, all pts in registers (N=512), no block syncs.
// ---------------------------------------------------------------------------
__global__ void __launch_bounds__(32) fps_warp_kernel(
    const float* __restrict__ xyz, int N, int npoint,
    int* __restrict__ idx_out, float* __restrict__ newxyz)
{
    const int b = blockIdx.x;
    const int lane = threadIdx.x;
    const float* P = xyz + (size_t)b * N * 3;

    float x[16], y[16], z[16], dist[16];
#pragma unroll
    for (int k = 0; k < 16; k++) {
        int p = lane + k * 32;
        x[k] = P[p * 3 + 0];
        y[k] = P[p * 3 + 1];
        z[k] = P[p * 3 + 2];
        dist[k] = 1e10f;
    }
    float fx = P[0], fy = P[1], fz = P[2];
    if (lane == 0) {
        idx_out[b * npoint] = 0;
        newxyz[(size_t)b * npoint * 3 + 0] = fx;
        newxyz[(size_t)b * npoint * 3 + 1] = fy;
        newxyz[(size_t)b * npoint * 3 + 2] = fz;
    }
    for (int it = 1; it < npoint; it++) {
        float best = -1.f;
        int bi = 0x7fffffff;
#pragma unroll
        for (int k = 0; k < 16; k++) {
            float dx = __fsub_rn(x[k], fx);
            float dy = __fsub_rn(y[k], fy);
            float dz = __fsub_rn(z[k], fz);
            float d = __fadd_rn(__fadd_rn(__fmul_rn(dx, dx), __fmul_rn(dy, dy)),
                                __fmul_rn(dz, dz));
            float nd = fminf(dist[k], d);
            dist[k] = nd;
            if (nd > best) { best = nd; bi = lane + k * 32; }
        }
#pragma unroll
        for (int o = 16; o > 0; o >>= 1) {
            float ov = __shfl_xor_sync(0xffffffffu, best, o);
            int   oi = __shfl_xor_sync(0xffffffffu, bi, o);
            if (ov > best || (ov == best && oi < bi)) { best = ov; bi = oi; }
        }
        fx = P[bi * 3 + 0];
        fy = P[bi * 3 + 1];
        fz = P[bi * 3 + 2];
        if (lane == 0) {
            idx_out[b * npoint + it] = bi;
            newxyz[((size_t)b * npoint + it) * 3 + 0] = fx;
            newxyz[((size_t)b * npoint + it) * 3 + 1] = fy;
            newxyz[((size_t)b * npoint + it) * 3 + 2] = fz;
        }
    }
}

// ---------------------------------------------------------------------------
// Ball query — one warp per center; first nsample (ascending) within radius.
// ---------------------------------------------------------------------------
__global__ void ballquery_kernel(const float* __restrict__ centers,
                                 const float* __restrict__ pts,
                                 int B, int S, int N, float r2, int nsample,
                                 int* __restrict__ out)
{
    int wg = (blockIdx.x * blockDim.x + threadIdx.x) >> 5;
    int lane = threadIdx.x & 31;
    if (wg >= B * S) return;
    int b = wg / S;
    const float* P = pts + (size_t)b * N * 3;
    float cx = centers[(size_t)wg * 3 + 0];
    float cy = centers[(size_t)wg * 3 + 1];
    float cz = centers[(size_t)wg * 3 + 2];
    int* o = out + (size_t)wg * nsample;

    int count = 0;
    int first = -1;
    for (int base = 0; base < N && count < nsample; base += 32) {
        int p = base + lane;
        bool inside = false;
        if (p < N) {
            float dx = __fsub_rn(cx, P[p * 3 + 0]);
            float dy = __fsub_rn(cy, P[p * 3 + 1]);
            float dz = __fsub_rn(cz, P[p * 3 + 2]);
            float d2 = __fadd_rn(__fadd_rn(__fmul_rn(dx, dx), __fmul_rn(dy, dy)),
                                 __fmul_rn(dz, dz));
            inside = d2 < r2;
        }
        unsigned m = __ballot_sync(0xffffffffu, inside);
        if (first < 0 && m) first = base + __ffs(m) - 1;
        if (inside) {
            int pos = count + __popc(m & ((1u << lane) - 1u));
            if (pos < nsample) o[pos] = p;
        }
        count += __popc(m);
    }
    int start = count < nsample ? count : nsample;
    for (int k = start + lane; k < nsample; k += 32) o[k] = first;
}

// ---------------------------------------------------------------------------
// Concat kernels
// ---------------------------------------------------------------------------
__global__ void concat_sa3_kernel(const float* __restrict__ xyz2,
                                  const float* __restrict__ f2,
                                  float* __restrict__ out, int R, int CF)
{
    int C = 3 + CF;
    unsigned total = (unsigned)R * C;
    unsigned stride = gridDim.x * blockDim.x;
    for (unsigned e = blockIdx.x * blockDim.x + threadIdx.x; e < total; e += stride) {
        int r = e / C;
        int c = e % C;
        out[e] = (c < 3) ? xyz2[(size_t)r * 3 + c] : f2[(size_t)r * CF + (c - 3)];
    }
}

__global__ void concat_comb_kernel(const float* __restrict__ gf,
                                   const float* __restrict__ of,
                                   float* __restrict__ out, int B, int C1, int C2)
{
    int C = C1 + C2;
    unsigned total = (unsigned)B * C;
    unsigned stride = gridDim.x * blockDim.x;
    for (unsigned e = blockIdx.x * blockDim.x + threadIdx.x; e < total; e += stride) {
        int b = e / C;
        int c = e % C;
        out[e] = (c < C1) ? gf[(size_t)b * C1 + c] : of[(size_t)b * C2 + (c - C1)];
    }
}

// ---------------------------------------------------------------------------
// Host orchestration
// ---------------------------------------------------------------------------
static inline int cdiv(long a, long b) { return (int)((a + b - 1) / b); }
static int ew_blocks(long total)
{
    int b = cdiv(total, 256);
    return b > 4096 ? 4096 : b;
}

struct GatherArgs {
    const int* idx; const float* pts; const float* ctr; const float* feats;
    int npts, bShift, nsShift, cf; float rad;
};

template<int BN_>
static void launch_tile(const float* X, const float* W, float* Y,
                        int M, int N, int K,
                        const float* inSum, const float* inSq, float invMin,
                        float* outSum, float* outSq,
                        const GatherArgs* ga)
{
    dim3 grid(cdiv(N, BN_), cdiv(M, 128));
    if (ga) {
        gemm_tile_kernel<BN_><<<grid, 256>>>(X, W, Y, M, N, K,
            inSum, inSq, invMin, outSum, outSq,
            ga->idx, ga->pts, ga->ctr, ga->feats,
            ga->npts, ga->bShift, ga->nsShift, ga->cf, ga->rad);
    } else {
        gemm_tile_kernel<BN_><<<grid, 256>>>(X, W, Y, M, N, K,
            inSum, inSq, invMin, outSum, outSq,
            nullptr, nullptr, nullptr, nullptr, 0, 0, 0, 0, 0.f);
    }
}

extern "C" void kernel_launch(void* const* d_in, const int* in_sizes, int n_in,
                              void* d_out, int out_size)
{
    (void)in_sizes; (void)n_in; (void)out_size;
    const float* obj   = (const float*)d_in[0];
    const float* grip  = (const float*)d_in[1];
    const float* sa1w0 = (const float*)d_in[2];
    const float* sa1w1 = (const float*)d_in[3];
    const float* sa1w2 = (const float*)d_in[4];
    const float* sa2w0 = (const float*)d_in[5];
    const float* sa2w1 = (const float*)d_in[6];
    const float* sa2w2 = (const float*)d_in[7];
    const float* sa3w0 = (const float*)d_in[8];
    const float* sa3w1 = (const float*)d_in[9];
    const float* sa3w2 = (const float*)d_in[10];
    const float* gew0  = (const float*)d_in[11];
    const float* gew1  = (const float*)d_in[12];
    const float* gew2  = (const float*)d_in[13];
    const float* hw0   = (const float*)d_in[14];
    const float* hb0   = (const float*)d_in[15];
    const float* hw1   = (const float*)d_in[16];
    const float* hb1   = (const float*)d_in[17];
    const float* hw2   = (const float*)d_in[18];
    const float* hb2   = (const float*)d_in[19];

    float *bufA, *bufB, *f1, *f2, *sa3in, *gfeat, *objf, *comb, *h0, *h1;
    float *xyz1, *xyz2, *bsum, *bsq;
    int *fps1, *fps2, *bq1, *bq2;
    cudaGetSymbolAddress((void**)&bufA,  g_bufA);
    cudaGetSymbolAddress((void**)&bufB,  g_bufB);
    cudaGetSymbolAddress((void**)&f1,    g_f1);
    cudaGetSymbolAddress((void**)&f2,    g_f2);
    cudaGetSymbolAddress((void**)&sa3in, g_sa3in);
    cudaGetSymbolAddress((void**)&gfeat, g_gfeat);
    cudaGetSymbolAddress((void**)&objf,  g_objfeat);
    cudaGetSymbolAddress((void**)&comb,  g_comb);
    cudaGetSymbolAddress((void**)&h0,    g_h0);
    cudaGetSymbolAddress((void**)&h1,    g_h1);
    cudaGetSymbolAddress((void**)&xyz1,  g_xyz1);
    cudaGetSymbolAddress((void**)&xyz2,  g_xyz2);
    cudaGetSymbolAddress((void**)&fps1,  g_fps1);
    cudaGetSymbolAddress((void**)&fps2,  g_fps2);
    cudaGetSymbolAddress((void**)&bq1,   g_bq1);
    cudaGetSymbolAddress((void**)&bq2,   g_bq2);
    cudaGetSymbolAddress((void**)&bsum,  g_bnsum);
    cudaGetSymbolAddress((void**)&bsq,   g_bnsq);

    const int B = 8, N0 = 20000, G = 512;
    const int S1 = 512, NS1 = 32, S2 = 128, NS2 = 64;
    const float r2_1 = (float)(0.2 * 0.2);
    const float r2_2 = (float)(0.4 * 0.4);

    // per-layer stat region offsets (channels)
    const int oGE0 = 0, oGE1 = 64, oGE2 = 192;           // 64,128,128
    const int oS10 = 320, oS11 = 384, oS12 = 448;        // 64,64,128
    const int oS20 = 576, oS21 = 704, oS22 = 832;        // 128,128,256
    const int oS30 = 1088, oS31 = 1344, oS32 = 1856;     // 256,512,1024

    bn_zero_kernel<<<cdiv(4096, 256), 256>>>(bsum, bsq, 4096);

    // ---------------- FPS ----------------
    cudaFuncSetAttribute(fps1_kernel, cudaFuncAttributeMaxDynamicSharedMemorySize,
                         N0 * (int)sizeof(float2));
    fps1_kernel<<<B, 512, N0 * sizeof(float2)>>>(obj, N0, S1, fps1, xyz1);
    fps_warp_kernel<<<B, 32>>>(xyz1, S1, S2, fps2, xyz2);

    // ---------------- ball queries ----------------
    ballquery_kernel<<<cdiv((long)B * S1 * 32, 128), 128>>>(xyz1, obj, B, S1, N0,
                                                            r2_1, NS1, bq1);
    ballquery_kernel<<<cdiv((long)B * S2 * 32, 128), 128>>>(xyz2, xyz1, B, S2, S1,
                                                            r2_2, NS2, bq2);

    // ---------------- gripper encoder ----------------
    {
        int M = B * G;  // 4096
        float iM = 1.f / (float)M;
        launch_tile<64>(grip, gew0, bufB, M, 64, 3,
                        nullptr, nullptr, 0.f, bsum + oGE0, bsq + oGE0, nullptr);
        launch_tile<128>(bufB, gew1, bufA, M, 128, 64,
                         bsum + oGE0, bsq + oGE0, iM, bsum + oGE1, bsq + oGE1, nullptr);
        launch_tile<128>(bufA, gew2, bufB, M, 128, 128,
                         bsum + oGE1, bsq + oGE1, iM, bsum + oGE2, bsq + oGE2, nullptr);
        maxpool_bn_kernel<<<ew_blocks((long)B * 128), 256>>>(bufB, gfeat, B, G, 128,
                                                             bsum + oGE2, bsq + oGE2, iM);
    }

    // ---------------- SA1 ----------------
    {
        int M = B * S1 * NS1;  // 131072
        float iM = 1.f / (float)M;
        GatherArgs ga = {bq1, obj, xyz1, nullptr, N0, 14, 5, 0, 0.2f};
        launch_tile<64>(nullptr, sa1w0, bufB, M, 64, 3,
                        nullptr, nullptr, 0.f, bsum + oS10, bsq + oS10, &ga);
        launch_tile<64>(bufB, sa1w1, bufA, M, 64, 64,
                        bsum + oS10, bsq + oS10, iM, bsum + oS11, bsq + oS11, nullptr);
        launch_tile<128>(bufA, sa1w2, bufB, M, 128, 64,
                         bsum + oS11, bsq + oS11, iM, bsum + oS12, bsq + oS12, nullptr);
        maxpool_bn_kernel<<<ew_blocks((long)B * S1 * 128), 256>>>(
            bufB, f1, B * S1, NS1, 128, bsum + oS12, bsq + oS12, iM);
    }

    // ---------------- SA2 ----------------
    {
        int M = B * S2 * NS2;  // 65536
        float iM = 1.f / (float)M;
        GatherArgs ga = {bq2, xyz1, xyz2, f1, S1, 13, 6, 128, 0.4f};
        launch_tile<128>(nullptr, sa2w0, bufB, M, 128, 131,
                         nullptr, nullptr, 0.f, bsum + oS20, bsq + oS20, &ga);
        launch_tile<128>(bufB, sa2w1, bufA, M, 128, 128,
                         bsum + oS20, bsq + oS20, iM, bsum + oS21, bsq + oS21, nullptr);
        launch_tile<128>(bufA, sa2w2, bufB, M, 256, 128,
                         bsum + oS21, bsq + oS21, iM, bsum + oS22, bsq + oS22, nullptr);
        maxpool_bn_kernel<<<ew_blocks((long)B * S2 * 256), 256>>>(
            bufB, f2, B * S2, NS2, 256, bsum + oS22, bsq + oS22, iM);
    }

    // ---------------- SA3 (group_all) ----------------
    {
        int M = B * S2;  // 1024
        float iM = 1.f / (float)M;
        concat_sa3_kernel<<<ew_blocks((long)M * 259), 256>>>(xyz2, f2, sa3in, M, 256);
        launch_tile<128>(sa3in, sa3w0, bufA, M, 256, 259,
                         nullptr, nullptr, 0.f, bsum + oS30, bsq + oS30, nullptr);
        launch_tile<128>(bufA, sa3w1, bufB, M, 512, 256,
                         bsum + oS30, bsq + oS30, iM, bsum + oS31, bsq + oS31, nullptr);
        launch_tile<128>(bufB, sa3w2, bufA, M, 1024, 512,
                         bsum + oS31, bsq + oS31, iM, bsum + oS32, bsq + oS32, nullptr);
        maxpool_bn_kernel<<<ew_blocks((long)B * 1024), 256>>>(
            bufA, objf, B, S2, 1024, bsum + oS32, bsq + oS32, iM);
    }

    // ---------------- head ----------------
    {
        concat_comb_kernel<<<ew_blocks((long)B * 1152), 256>>>(gfeat, objf, comb,
                                                               B, 128, 1024);
        bn_col_kernel<<<cdiv(1152, 256), 256>>>(comb, B, 1152, 0);
        gemm_small_kernel<<<cdiv(512, 8), 256>>>(comb, hw0, hb0, h0, B, 512, 1152, 0);
        bn_col_kernel<<<cdiv(512, 256), 256>>>(h0, B, 512, 1);
        gemm_small_kernel<<<cdiv(256, 8), 256>>>(h0, hw1, hb1, h1, B, 256, 512, 0);
        bn_col_kernel<<<cdiv(256, 256), 256>>>(h1, B, 256, 1);
        gemm_small_kernel<<<1, 256>>>(h1, hw2, hb2, (float*)d_out, B, 1, 256, 1);
    }
}

// round 7
// speedup vs baseline: 1.1372x; 1.1372x over previous
#include <cuda_runtime.h>
#include <math.h>

#define BN_EPS 1e-5f

// ---------------------------------------------------------------------------
// Static device scratch
// ---------------------------------------------------------------------------
__device__ float g_bufA[131072 * 128];
__device__ float g_bufB[131072 * 128];
__device__ float g_f1[8 * 512 * 128];
__device__ float g_f2[8 * 128 * 256];
__device__ float g_sa3in[1024 * 259];
__device__ float g_gfeat[8 * 128];
__device__ float g_objfeat[8 * 1024];
__device__ float g_comb[8 * 1152];
__device__ float g_h0[8 * 512];
__device__ float g_h1[8 * 256];
__device__ float g_xyz1[8 * 512 * 3];
__device__ float g_xyz2[8 * 128 * 3];
__device__ int   g_fps1[8 * 512];
__device__ int   g_fps2[8 * 128];
__device__ int   g_bq1[8 * 512 * 32];
__device__ int   g_bq2[8 * 128 * 64];
__device__ float g_bnsum[4096];
__device__ float g_bnsq[4096];

// ---------------------------------------------------------------------------
// Tiled GEMM:  Y[M,N] = f(X)[M,K] * W[N,K]^T
//  BM=128, BN=64, BK=16, 256 threads, 8x4 microtile, single-buffered smem.
//  Input modes:
//    gather (gIdx != null): A row built by ball-query point gather
//    bn     (inSum != null): A = relu((X - mean)*inv), mean/inv from raw sums
//    plain  otherwise
//  Epilogue: optional per-column sum/sumsq accumulation for next layer's BN.
// ---------------------------------------------------------------------------
__global__ __launch_bounds__(256) void gemm_tile_kernel(
    const float* __restrict__ X, const float* __restrict__ W,
    float* __restrict__ Y, int M, int N, int K,
    const float* __restrict__ inSum, const float* __restrict__ inSq, float invMin,
    float* __restrict__ outSum, float* __restrict__ outSq,
    const int* __restrict__ gIdx, const float* __restrict__ gPts,
    const float* __restrict__ gCtr, const float* __restrict__ gFeats,
    int gNpts, int gBShift, int gNsShift, int gCF, float gRad)
{
    __shared__ __align__(16) float As[16][132];
    __shared__ __align__(16) float Bs[16][68];
    __shared__ float sMean[512];
    __shared__ float sInv[512];
    __shared__ int   sPid[128];
    __shared__ float sSum[64];
    __shared__ float sSq[64];

    const int bm = blockIdx.y * 128;
    const int bn = blockIdx.x * 64;
    const int t  = threadIdx.x;
    const int ty = t >> 4;   // 0..15
    const int tx = t & 15;   // 0..15

    const bool useBn = (inSum != nullptr);
    const bool useG  = (gIdx != nullptr);

    if (useBn) {
        for (int k = t; k < K; k += 256) {
            float m = inSum[k] * invMin;
            float var = fmaxf(inSq[k] * invMin - m * m, 0.f);
            sMean[k] = m;
            sInv[k] = 1.f / sqrtf(var + BN_EPS);
        }
    }
    if (useG && t < 128) {
        int g = bm + t;
        int pid = 0;
        if (g < M) pid = (g >> gBShift) * gNpts + gIdx[g];
        sPid[t] = pid;
    }
    if (useBn || useG) __syncthreads();

    float acc[8][4];
#pragma unroll
    for (int i = 0; i < 8; i++)
#pragma unroll
        for (int j = 0; j < 4; j++) acc[i][j] = 0.f;

    for (int k0 = 0; k0 < K; k0 += 16) {
        // load X tile (128 x 16)
#pragma unroll
        for (int i = 0; i < 8; i++) {
            int lin = i * 256 + t;
            int r = lin >> 4, c = lin & 15;
            int gm = bm + r, gk = k0 + c;
            float v = 0.f;
            if (gk < K && gm < M) {
                if (useG) {
                    int pid = sPid[r];
                    if (gk < 3) {
                        int cr = gm >> gNsShift;
                        v = __fdiv_rn(__fsub_rn(gPts[(size_t)pid * 3 + gk],
                                                gCtr[(size_t)cr * 3 + gk]), gRad);
                    } else {
                        v = gFeats[(size_t)pid * gCF + (gk - 3)];
                    }
                } else {
                    v = X[(size_t)gm * K + gk];
                    if (useBn) v = fmaxf(0.f, (v - sMean[gk]) * sInv[gk]);
                }
            }
            As[c][r] = v;
        }
        // load W tile (64 x 16)
#pragma unroll
        for (int i = 0; i < 4; i++) {
            int lin = i * 256 + t;
            int r = lin >> 4, c = lin & 15;
            int gn = bn + r, gk = k0 + c;
            Bs[c][r] = (gk < K && gn < N) ? W[(size_t)gn * K + gk] : 0.f;
        }
        __syncthreads();
#pragma unroll
        for (int kk = 0; kk < 16; kk++) {
            float4 a0 = *reinterpret_cast<const float4*>(&As[kk][ty * 8]);
            float4 a1 = *reinterpret_cast<const float4*>(&As[kk][ty * 8 + 4]);
            float4 bv = *reinterpret_cast<const float4*>(&Bs[kk][tx * 4]);
            float a[8] = {a0.x, a0.y, a0.z, a0.w, a1.x, a1.y, a1.z, a1.w};
            float b[4] = {bv.x, bv.y, bv.z, bv.w};
#pragma unroll
            for (int i = 0; i < 8; i++)
#pragma unroll
                for (int j = 0; j < 4; j++)
                    acc[i][j] = fmaf(a[i], b[j], acc[i][j]);
        }
        __syncthreads();
    }

    // epilogue: store + optional per-column stats
    float colS[4] = {0.f, 0.f, 0.f, 0.f};
    float colQ[4] = {0.f, 0.f, 0.f, 0.f};
#pragma unroll
    for (int i = 0; i < 8; i++) {
        int gm = bm + ty * 8 + i;
        if (gm >= M) continue;
#pragma unroll
        for (int j = 0; j < 4; j++) {
            int gn = bn + tx * 4 + j;
            if (gn >= N) continue;
            float v = acc[i][j];
            Y[(size_t)gm * N + gn] = v;
            colS[j] += v;
            colQ[j] = fmaf(v, v, colQ[j]);
        }
    }

    if (outSum) {
#pragma unroll
        for (int j = 0; j < 4; j++) {
            colS[j] += __shfl_down_sync(0xffffffffu, colS[j], 16);
            colQ[j] += __shfl_down_sync(0xffffffffu, colQ[j], 16);
        }
        if (t < 64) { sSum[t] = 0.f; sSq[t] = 0.f; }
        __syncthreads();
        if ((t & 31) < 16) {
#pragma unroll
            for (int j = 0; j < 4; j++) {
                atomicAdd(&sSum[tx * 4 + j], colS[j]);
                atomicAdd(&sSq[tx * 4 + j], colQ[j]);
            }
        }
        __syncthreads();
        if (t < 64) {
            int gn = bn + t;
            if (gn < N) {
                atomicAdd(&outSum[gn], sSum[t]);
                atomicAdd(&outSq[gn], sSq[t]);
            }
        }
    }
}

// ---------------------------------------------------------------------------
// Small-M GEMM for the head (M <= 8): warp-per-column, X cached in smem.
// ---------------------------------------------------------------------------
__global__ __launch_bounds__(256) void gemm_small_kernel(
    const float* __restrict__ X, const float* __restrict__ W,
    const float* __restrict__ bias, float* __restrict__ Y,
    int M, int N, int K, int relu)
{
    __shared__ float sX[8 * 1152];
    for (int i = threadIdx.x; i < M * K; i += 256) sX[i] = X[i];
    __syncthreads();
    int warp = threadIdx.x >> 5, lane = threadIdx.x & 31;
    int n = blockIdx.x * 8 + warp;
    if (n >= N) return;
    float acc[8];
#pragma unroll
    for (int m = 0; m < 8; m++) acc[m] = 0.f;
    for (int k = lane; k < K; k += 32) {
        float wv = W[(size_t)n * K + k];
#pragma unroll
        for (int m = 0; m < 8; m++)
            acc[m] = fmaf(sX[m * K + k], wv, acc[m]);
    }
#pragma unroll
    for (int m = 0; m < 8; m++) {
#pragma unroll
        for (int o = 16; o > 0; o >>= 1)
            acc[m] += __shfl_down_sync(0xffffffffu, acc[m], o);
    }
    if (lane == 0) {
        for (int m = 0; m < M; m++) {
            float v = acc[m] + bias[n];
            if (relu) v = fmaxf(v, 0.f);
            Y[(size_t)m * N + n] = v;
        }
    }
}

// ---------------------------------------------------------------------------
// BN helpers
// ---------------------------------------------------------------------------
__global__ void bn_zero_kernel(float* s, float* q, int C)
{
    int i = blockIdx.x * blockDim.x + threadIdx.x;
    if (i < C) { s[i] = 0.f; q[i] = 0.f; }
}

__global__ void bn_col_kernel(float* __restrict__ X, int M, int C, int relu)
{
    int c = blockIdx.x * blockDim.x + threadIdx.x;
    if (c >= C) return;
    float s = 0.f, q = 0.f;
    for (int m = 0; m < M; m++) {
        float v = X[(size_t)m * C + c];
        s += v;
        q = fmaf(v, v, q);
    }
    float mean = s / (float)M;
    float var = fmaxf(q / (float)M - mean * mean, 0.f);
    float inv = 1.f / sqrtf(var + BN_EPS);
    for (int m = 0; m < M; m++) {
        float v = (X[(size_t)m * C + c] - mean) * inv;
        if (relu) v = fmaxf(v, 0.f);
        X[(size_t)m * C + c] = v;
    }
}

// ---------------------------------------------------------------------------
// Max pool over group axis + BN(from raw sums) + ReLU
// ---------------------------------------------------------------------------
__global__ void maxpool_bn_kernel(const float* __restrict__ X, float* __restrict__ Y,
                                  int R, int ns, int C,
                                  const float* __restrict__ gsum,
                                  const float* __restrict__ gsq, float invM)
{
    unsigned total = (unsigned)R * C;
    unsigned stride = gridDim.x * blockDim.x;
    for (unsigned e = blockIdx.x * blockDim.x + threadIdx.x; e < total; e += stride) {
        int r = e / C;
        int c = e % C;
        const float* p = X + ((size_t)r * ns) * C + c;
        float m = -3.402823466e38f;
        for (int j = 0; j < ns; j++) m = fmaxf(m, p[(size_t)j * C]);
        float mean = gsum[c] * invM;
        float var = fmaxf(gsq[c] * invM - mean * mean, 0.f);
        float inv = 1.f / sqrtf(var + BN_EPS);
        Y[e] = fmaxf(0.f, (m - mean) * inv);
    }
}

// ---------------------------------------------------------------------------
// FPS1: one block per batch, 512 threads, 40 pts/thread, xy in 160KB smem.
// ---------------------------------------------------------------------------
__global__ void __launch_bounds__(512) fps1_kernel(
    const float* __restrict__ xyz, int N, int npoint,
    int* __restrict__ idx_out, float* __restrict__ newxyz)
{
    extern __shared__ float2 sxy[];
    const int b = blockIdx.x;
    const int T = 512;
    const int t = threadIdx.x;
    const float* P = xyz + (size_t)b * N * 3;

    __shared__ float s_v[16];
    __shared__ int   s_i[16];
    __shared__ float s_far[3];

    for (int p = t; p < N; p += T)
        sxy[p] = make_float2(P[p * 3 + 0], P[p * 3 + 1]);

    float zreg[40];
    float dist[40];
#pragma unroll
    for (int k = 0; k < 40; k++) {
        int p = t + k * T;
        zreg[k] = (p < N) ? P[p * 3 + 2] : 0.f;
        dist[k] = 1e10f;
    }
    if (t == 0) {
        idx_out[b * npoint] = 0;
        float fx = P[0], fy = P[1], fz = P[2];
        newxyz[(size_t)b * npoint * 3 + 0] = fx;
        newxyz[(size_t)b * npoint * 3 + 1] = fy;
        newxyz[(size_t)b * npoint * 3 + 2] = fz;
        s_far[0] = fx; s_far[1] = fy; s_far[2] = fz;
    }
    __syncthreads();

    for (int it = 1; it < npoint; it++) {
        float fx = s_far[0], fy = s_far[1], fz = s_far[2];
        float best = -1.f;
        int bi = 0x7fffffff;
#pragma unroll
        for (int k = 0; k < 40; k++) {
            int p = t + k * T;
            if (p < N) {
                float2 xy = sxy[p];
                float dx = __fsub_rn(xy.x, fx);
                float dy = __fsub_rn(xy.y, fy);
                float dz = __fsub_rn(zreg[k], fz);
                float d = __fadd_rn(__fadd_rn(__fmul_rn(dx, dx), __fmul_rn(dy, dy)),
                                    __fmul_rn(dz, dz));
                float nd = fminf(dist[k], d);
                dist[k] = nd;
                if (nd > best) { best = nd; bi = p; }
            }
        }
#pragma unroll
        for (int o = 16; o > 0; o >>= 1) {
            float ov = __shfl_down_sync(0xffffffffu, best, o);
            int   oi = __shfl_down_sync(0xffffffffu, bi, o);
            if (ov > best || (ov == best && oi < bi)) { best = ov; bi = oi; }
        }
        if ((t & 31) == 0) { s_v[t >> 5] = best; s_i[t >> 5] = bi; }
        __syncthreads();
        if (t < 32) {
            best = (t < 16) ? s_v[t] : -1.f;
            bi   = (t < 16) ? s_i[t] : 0x7fffffff;
#pragma unroll
            for (int o = 8; o > 0; o >>= 1) {
                float ov = __shfl_down_sync(0xffffffffu, best, o);
                int   oi = __shfl_down_sync(0xffffffffu, bi, o);
                if (ov > best || (ov == best && oi < bi)) { best = ov; bi = oi; }
            }
            if (t == 0) {
                float2 fxy = sxy[bi];
                float fz2 = P[bi * 3 + 2];
                idx_out[b * npoint + it] = bi;
                newxyz[((size_t)b * npoint + it) * 3 + 0] = fxy.x;
                newxyz[((size_t)b * npoint + it) * 3 + 1] = fxy.y;
                newxyz[((size_t)b * npoint + it) * 3 + 2] = fz2;
                s_far[0] = fxy.x; s_far[1] = fxy.y; s_far[2] = fz2;
            }
        }
        __syncthreads();
    }
}

// ---------------------------------------------------------------------------
// FPS2: one warp per batch, all pts in registers (N=512), no block syncs.
// ---------------------------------------------------------------------------
__global__ void __launch_bounds__(32) fps_warp_kernel(
    const float* __restrict__ xyz, int N, int npoint,
    int* __restrict__ idx_out, float* __restrict__ newxyz)
{
    const int b = blockIdx.x;
    const int lane = threadIdx.x;
    const float* P = xyz + (size_t)b * N * 3;

    float x[16], y[16], z[16], dist[16];
#pragma unroll
    for (int k = 0; k < 16; k++) {
        int p = lane + k * 32;
        x[k] = P[p * 3 + 0];
        y[k] = P[p * 3 + 1];
        z[k] = P[p * 3 + 2];
        dist[k] = 1e10f;
    }
    float fx = P[0], fy = P[1], fz = P[2];
    if (lane == 0) {
        idx_out[b * npoint] = 0;
        newxyz[(size_t)b * npoint * 3 + 0] = fx;
        newxyz[(size_t)b * npoint * 3 + 1] = fy;
        newxyz[(size_t)b * npoint * 3 + 2] = fz;
    }
    for (int it = 1; it < npoint; it++) {
        float best = -1.f;
        int bi = 0x7fffffff;
#pragma unroll
        for (int k = 0; k < 16; k++) {
            float dx = __fsub_rn(x[k], fx);
            float dy = __fsub_rn(y[k], fy);
            float dz = __fsub_rn(z[k], fz);
            float d = __fadd_rn(__fadd_rn(__fmul_rn(dx, dx), __fmul_rn(dy, dy)),
                                __fmul_rn(dz, dz));
            float nd = fminf(dist[k], d);
            dist[k] = nd;
            if (nd > best) { best = nd; bi = lane + k * 32; }
        }
#pragma unroll
        for (int o = 16; o > 0; o >>= 1) {
            float ov = __shfl_xor_sync(0xffffffffu, best, o);
            int   oi = __shfl_xor_sync(0xffffffffu, bi, o);
            if (ov > best || (ov == best && oi < bi)) { best = ov; bi = oi; }
        }
        fx = P[bi * 3 + 0];
        fy = P[bi * 3 + 1];
        fz = P[bi * 3 + 2];
        if (lane == 0) {
            idx_out[b * npoint + it] = bi;
            newxyz[((size_t)b * npoint + it) * 3 + 0] = fx;
            newxyz[((size_t)b * npoint + it) * 3 + 1] = fy;
            newxyz[((size_t)b * npoint + it) * 3 + 2] = fz;
        }
    }
}

// ---------------------------------------------------------------------------
// Ball query — one warp per center; MLP-batched scan of 256-point superchunks.
// Selection semantics: first nsample indices (ascending) with d2 < r2,
// padded with the first valid index.
// ---------------------------------------------------------------------------
__global__ __launch_bounds__(256) void ballquery_kernel(
    const float* __restrict__ centers, const float* __restrict__ pts,
    int B, int S, int N, float r2, int nsample, int* __restrict__ out)
{
    int wg = (blockIdx.x * blockDim.x + threadIdx.x) >> 5;
    int lane = threadIdx.x & 31;
    if (wg >= B * S) return;
    int b = wg / S;
    const float* P = pts + (size_t)b * N * 3;
    float cx = centers[(size_t)wg * 3 + 0];
    float cy = centers[(size_t)wg * 3 + 1];
    float cz = centers[(size_t)wg * 3 + 2];
    int* o = out + (size_t)wg * nsample;

    int count = 0;
    int first = -1;
    for (int base = 0; base < N && count < nsample; base += 256) {
        bool ins[8];
        // 8 independent distance computations -> 24 outstanding loads
#pragma unroll
        for (int j = 0; j < 8; j++) {
            int p = base + j * 32 + lane;
            bool inside = false;
            if (p < N) {
                float dx = __fsub_rn(cx, P[p * 3 + 0]);
                float dy = __fsub_rn(cy, P[p * 3 + 1]);
                float dz = __fsub_rn(cz, P[p * 3 + 2]);
                float d2 = __fadd_rn(__fadd_rn(__fmul_rn(dx, dx), __fmul_rn(dy, dy)),
                                     __fmul_rn(dz, dz));
                inside = d2 < r2;
            }
            ins[j] = inside;
        }
        // sequential bookkeeping (cheap ALU/ballot only)
#pragma unroll
        for (int j = 0; j < 8; j++) {
            unsigned m = __ballot_sync(0xffffffffu, ins[j]);
            if (first < 0 && m) first = base + j * 32 + __ffs(m) - 1;
            if (ins[j]) {
                int pos = count + __popc(m & ((1u << lane) - 1u));
                if (pos < nsample) o[pos] = base + j * 32 + lane;
            }
            count += __popc(m);
        }
    }
    int start = count < nsample ? count : nsample;
    for (int k = start + lane; k < nsample; k += 32) o[k] = first;
}

// ---------------------------------------------------------------------------
// Concat kernels
// ---------------------------------------------------------------------------
__global__ void concat_sa3_kernel(const float* __restrict__ xyz2,
                                  const float* __restrict__ f2,
                                  float* __restrict__ out, int R, int CF)
{
    int C = 3 + CF;
    unsigned total = (unsigned)R * C;
    unsigned stride = gridDim.x * blockDim.x;
    for (unsigned e = blockIdx.x * blockDim.x + threadIdx.x; e < total; e += stride) {
        int r = e / C;
        int c = e % C;
        out[e] = (c < 3) ? xyz2[(size_t)r * 3 + c] : f2[(size_t)r * CF + (c - 3)];
    }
}

__global__ void concat_comb_kernel(const float* __restrict__ gf,
                                   const float* __restrict__ of,
                                   float* __restrict__ out, int B, int C1, int C2)
{
    int C = C1 + C2;
    unsigned total = (unsigned)B * C;
    unsigned stride = gridDim.x * blockDim.x;
    for (unsigned e = blockIdx.x * blockDim.x + threadIdx.x; e < total; e += stride) {
        int b = e / C;
        int c = e % C;
        out[e] = (c < C1) ? gf[(size_t)b * C1 + c] : of[(size_t)b * C2 + (c - C1)];
    }
}

// ---------------------------------------------------------------------------
// Host orchestration
// ---------------------------------------------------------------------------
static inline int cdiv(long a, long b) { return (int)((a + b - 1) / b); }
static int ew_blocks(long total)
{
    int b = cdiv(total, 256);
    return b > 4096 ? 4096 : b;
}

struct GatherArgs {
    const int* idx; const float* pts; const float* ctr; const float* feats;
    int npts, bShift, nsShift, cf; float rad;
};

static void launch_tile(const float* X, const float* W, float* Y,
                        int M, int N, int K,
                        const float* inSum, const float* inSq, float invMin,
                        float* outSum, float* outSq,
                        const GatherArgs* ga)
{
    dim3 grid(cdiv(N, 64), cdiv(M, 128));
    if (ga) {
        gemm_tile_kernel<<<grid, 256>>>(X, W, Y, M, N, K,
            inSum, inSq, invMin, outSum, outSq,
            ga->idx, ga->pts, ga->ctr, ga->feats,
            ga->npts, ga->bShift, ga->nsShift, ga->cf, ga->rad);
    } else {
        gemm_tile_kernel<<<grid, 256>>>(X, W, Y, M, N, K,
            inSum, inSq, invMin, outSum, outSq,
            nullptr, nullptr, nullptr, nullptr, 0, 0, 0, 0, 0.f);
    }
}

extern "C" void kernel_launch(void* const* d_in, const int* in_sizes, int n_in,
                              void* d_out, int out_size)
{
    (void)in_sizes; (void)n_in; (void)out_size;
    const float* obj   = (const float*)d_in[0];
    const float* grip  = (const float*)d_in[1];
    const float* sa1w0 = (const float*)d_in[2];
    const float* sa1w1 = (const float*)d_in[3];
    const float* sa1w2 = (const float*)d_in[4];
    const float* sa2w0 = (const float*)d_in[5];
    const float* sa2w1 = (const float*)d_in[6];
    const float* sa2w2 = (const float*)d_in[7];
    const float* sa3w0 = (const float*)d_in[8];
    const float* sa3w1 = (const float*)d_in[9];
    const float* sa3w2 = (const float*)d_in[10];
    const float* gew0  = (const float*)d_in[11];
    const float* gew1  = (const float*)d_in[12];
    const float* gew2  = (const float*)d_in[13];
    const float* hw0   = (const float*)d_in[14];
    const float* hb0   = (const float*)d_in[15];
    const float* hw1   = (const float*)d_in[16];
    const float* hb1   = (const float*)d_in[17];
    const float* hw2   = (const float*)d_in[18];
    const float* hb2   = (const float*)d_in[19];

    float *bufA, *bufB, *f1, *f2, *sa3in, *gfeat, *objf, *comb, *h0, *h1;
    float *xyz1, *xyz2, *bsum, *bsq;
    int *fps1, *fps2, *bq1, *bq2;
    cudaGetSymbolAddress((void**)&bufA,  g_bufA);
    cudaGetSymbolAddress((void**)&bufB,  g_bufB);
    cudaGetSymbolAddress((void**)&f1,    g_f1);
    cudaGetSymbolAddress((void**)&f2,    g_f2);
    cudaGetSymbolAddress((void**)&sa3in, g_sa3in);
    cudaGetSymbolAddress((void**)&gfeat, g_gfeat);
    cudaGetSymbolAddress((void**)&objf,  g_objfeat);
    cudaGetSymbolAddress((void**)&comb,  g_comb);
    cudaGetSymbolAddress((void**)&h0,    g_h0);
    cudaGetSymbolAddress((void**)&h1,    g_h1);
    cudaGetSymbolAddress((void**)&xyz1,  g_xyz1);
    cudaGetSymbolAddress((void**)&xyz2,  g_xyz2);
    cudaGetSymbolAddress((void**)&fps1,  g_fps1);
    cudaGetSymbolAddress((void**)&fps2,  g_fps2);
    cudaGetSymbolAddress((void**)&bq1,   g_bq1);
    cudaGetSymbolAddress((void**)&bq2,   g_bq2);
    cudaGetSymbolAddress((void**)&bsum,  g_bnsum);
    cudaGetSymbolAddress((void**)&bsq,   g_bnsq);

    const int B = 8, N0 = 20000, G = 512;
    const int S1 = 512, NS1 = 32, S2 = 128, NS2 = 64;
    const float r2_1 = (float)(0.2 * 0.2);
    const float r2_2 = (float)(0.4 * 0.4);

    // per-layer stat region offsets (channels)
    const int oGE0 = 0, oGE1 = 64, oGE2 = 192;           // 64,128,128
    const int oS10 = 320, oS11 = 384, oS12 = 448;        // 64,64,128
    const int oS20 = 576, oS21 = 704, oS22 = 832;        // 128,128,256
    const int oS30 = 1088, oS31 = 1344, oS32 = 1856;     // 256,512,1024

    bn_zero_kernel<<<cdiv(4096, 256), 256>>>(bsum, bsq, 4096);

    // ---------------- FPS ----------------
    cudaFuncSetAttribute(fps1_kernel, cudaFuncAttributeMaxDynamicSharedMemorySize,
                         N0 * (int)sizeof(float2));
    fps1_kernel<<<B, 512, N0 * sizeof(float2)>>>(obj, N0, S1, fps1, xyz1);
    fps_warp_kernel<<<B, 32>>>(xyz1, S1, S2, fps2, xyz2);

    // ---------------- ball queries ----------------
    ballquery_kernel<<<cdiv((long)B * S1 * 32, 256), 256>>>(xyz1, obj, B, S1, N0,
                                                            r2_1, NS1, bq1);
    ballquery_kernel<<<cdiv((long)B * S2 * 32, 256), 256>>>(xyz2, xyz1, B, S2, S1,
                                                            r2_2, NS2, bq2);

    // ---------------- gripper encoder ----------------
    {
        int M = B * G;  // 4096
        float iM = 1.f / (float)M;
        launch_tile(grip, gew0, bufB, M, 64, 3,
                    nullptr, nullptr, 0.f, bsum + oGE0, bsq + oGE0, nullptr);
        launch_tile(bufB, gew1, bufA, M, 128, 64,
                    bsum + oGE0, bsq + oGE0, iM, bsum + oGE1, bsq + oGE1, nullptr);
        launch_tile(bufA, gew2, bufB, M, 128, 128,
                    bsum + oGE1, bsq + oGE1, iM, bsum + oGE2, bsq + oGE2, nullptr);
        maxpool_bn_kernel<<<ew_blocks((long)B * 128), 256>>>(bufB, gfeat, B, G, 128,
                                                             bsum + oGE2, bsq + oGE2, iM);
    }

    // ---------------- SA1 ----------------
    {
        int M = B * S1 * NS1;  // 131072
        float iM = 1.f / (float)M;
        GatherArgs ga = {bq1, obj, xyz1, nullptr, N0, 14, 5, 0, 0.2f};
        launch_tile(nullptr, sa1w0, bufB, M, 64, 3,
                    nullptr, nullptr, 0.f, bsum + oS10, bsq + oS10, &ga);
        launch_tile(bufB, sa1w1, bufA, M, 64, 64,
                    bsum + oS10, bsq + oS10, iM, bsum + oS11, bsq + oS11, nullptr);
        launch_tile(bufA, sa1w2, bufB, M, 128, 64,
                    bsum + oS11, bsq + oS11, iM, bsum + oS12, bsq + oS12, nullptr);
        maxpool_bn_kernel<<<ew_blocks((long)B * S1 * 128), 256>>>(
            bufB, f1, B * S1, NS1, 128, bsum + oS12, bsq + oS12, iM);
    }

    // ---------------- SA2 ----------------
    {
        int M = B * S2 * NS2;  // 65536
        float iM = 1.f / (float)M;
        GatherArgs ga = {bq2, xyz1, xyz2, f1, S1, 13, 6, 128, 0.4f};
        launch_tile(nullptr, sa2w0, bufB, M, 128, 131,
                    nullptr, nullptr, 0.f, bsum + oS20, bsq + oS20, &ga);
        launch_tile(bufB, sa2w1, bufA, M, 128, 128,
                    bsum + oS20, bsq + oS20, iM, bsum + oS21, bsq + oS21, nullptr);
        launch_tile(bufA, sa2w2, bufB, M, 256, 128,
                    bsum + oS21, bsq + oS21, iM, bsum + oS22, bsq + oS22, nullptr);
        maxpool_bn_kernel<<<ew_blocks((long)B * S2 * 256), 256>>>(
            bufB, f2, B * S2, NS2, 256, bsum + oS22, bsq + oS22, iM);
    }

    // ---------------- SA3 (group_all) ----------------
    {
        int M = B * S2;  // 1024
        float iM = 1.f / (float)M;
        concat_sa3_kernel<<<ew_blocks((long)M * 259), 256>>>(xyz2, f2, sa3in, M, 256);
        launch_tile(sa3in, sa3w0, bufA, M, 256, 259,
                    nullptr, nullptr, 0.f, bsum + oS30, bsq + oS30, nullptr);
        launch_tile(bufA, sa3w1, bufB, M, 512, 256,
                    bsum + oS30, bsq + oS30, iM, bsum + oS31, bsq + oS31, nullptr);
        launch_tile(bufB, sa3w2, bufA, M, 1024, 512,
                    bsum + oS31, bsq + oS31, iM, bsum + oS32, bsq + oS32, nullptr);
        maxpool_bn_kernel<<<ew_blocks((long)B * 1024), 256>>>(
            bufA, objf, B, S2, 1024, bsum + oS32, bsq + oS32, iM);
    }

    // ---------------- head ----------------
    {
        concat_comb_kernel<<<ew_blocks((long)B * 1152), 256>>>(gfeat, objf, comb,
                                                               B, 128, 1024);
        bn_col_kernel<<<cdiv(1152, 256), 256>>>(comb, B, 1152, 0);
        gemm_small_kernel<<<cdiv(512, 8), 256>>>(comb, hw0, hb0, h0, B, 512, 1152, 0);
        bn_col_kernel<<<cdiv(512, 256), 256>>>(h0, B, 512, 1);
        gemm_small_kernel<<<cdiv(256, 8), 256>>>(h0, hw1, hb1, h1, B, 256, 512, 0);
        bn_col_kernel<<<cdiv(256, 256), 256>>>(h1, B, 256, 1);
        gemm_small_kernel<<<1, 256>>>(h1, hw2, hb2, (float*)d_out, B, 1, 256, 1);
    }
}

// round 8
// speedup vs baseline: 1.4712x; 1.2937x over previous
#include <cuda_runtime.h>
#include <math.h>

#define BN_EPS 1e-5f

// ---- packed fp32x2 helpers (sm_103a dual-FP32 pipe) ----
#define PACK_F32X2(out, lo, hi) \
    asm("mov.b64 %0, {%1, %2};" : "=l"(out) : "r"(lo), "r"(hi))
#define UNPACK_F32X2(lo, hi, in) \
    asm("mov.b64 {%0, %1}, %2;" : "=r"(lo), "=r"(hi) : "l"(in))
#define ADD_F32X2(out, a, b) \
    asm("add.rn.f32x2 %0, %1, %2;" : "=l"(out) : "l"(a), "l"(b))
#define MUL_F32X2(out, a, b) \
    asm("mul.rn.f32x2 %0, %1, %2;" : "=l"(out) : "l"(a), "l"(b))
#define FMA_F32X2(d, a, b) \
    asm("fma.rn.f32x2 %0, %1, %2, %0;" : "+l"(d) : "l"(a), "l"(b))

// ---------------------------------------------------------------------------
// Static device scratch
// ---------------------------------------------------------------------------
__device__ float g_bufA[131072 * 128];
__device__ float g_bufB[131072 * 128];
__device__ float g_f1[8 * 512 * 128];
__device__ float g_f2[8 * 128 * 256];
__device__ float g_sa3in[1024 * 259];
__device__ float g_gfeat[8 * 128];
__device__ float g_objfeat[8 * 1024];
__device__ float g_comb[8 * 1152];
__device__ float g_h0[8 * 512];
__device__ float g_h1[8 * 256];
__device__ float g_xyz1[8 * 512 * 3];
__device__ float g_xyz2[8 * 128 * 3];
__device__ int   g_fps1[8 * 512];
__device__ int   g_fps2[8 * 128];
__device__ int   g_bq1[8 * 512 * 32];
__device__ int   g_bq2[8 * 128 * 64];
__device__ float g_bnsum[4096];
__device__ float g_bnsq[4096];

// ---------------------------------------------------------------------------
// Tiled GEMM:  Y[M,N] = f(X)[M,K] * W[N,K]^T
//  BM=128, BN=64, BK=16, 256 threads, 8x4 microtile, f32x2 packed FMA.
//  Input modes: gather (ball-query fusion) / bn (relu((x-mean)*inv)) / plain.
//  Epilogue: optional per-column sum/sumsq accumulation for next layer's BN.
// ---------------------------------------------------------------------------
__global__ __launch_bounds__(256) void gemm_tile_kernel(
    const float* __restrict__ X, const float* __restrict__ W,
    float* __restrict__ Y, int M, int N, int K,
    const float* __restrict__ inSum, const float* __restrict__ inSq, float invMin,
    float* __restrict__ outSum, float* __restrict__ outSq,
    const int* __restrict__ gIdx, const float* __restrict__ gPts,
    const float* __restrict__ gCtr, const float* __restrict__ gFeats,
    int gNpts, int gBShift, int gNsShift, int gCF, float gRad)
{
    __shared__ __align__(16) float As[16][132];
    __shared__ __align__(16) float Bs[16][68];
    __shared__ float sMean[512];
    __shared__ float sInv[512];
    __shared__ int   sPid[128];
    __shared__ float sSum[64];
    __shared__ float sSq[64];

    const int bm = blockIdx.y * 128;
    const int bn = blockIdx.x * 64;
    const int t  = threadIdx.x;
    const int ty = t >> 4;   // 0..15
    const int tx = t & 15;   // 0..15

    const bool useBn = (inSum != nullptr);
    const bool useG  = (gIdx != nullptr);

    if (useBn) {
        for (int k = t; k < K; k += 256) {
            float m = inSum[k] * invMin;
            float var = fmaxf(inSq[k] * invMin - m * m, 0.f);
            sMean[k] = m;
            sInv[k] = 1.f / sqrtf(var + BN_EPS);
        }
    }
    if (useG && t < 128) {
        int g = bm + t;
        int pid = 0;
        if (g < M) pid = (g >> gBShift) * gNpts + gIdx[g];
        sPid[t] = pid;
    }
    if (useBn || useG) __syncthreads();

    // packed accumulators: acc2[ip][j] = (acc[2ip][j], acc[2ip+1][j])
    unsigned long long acc2[4][4];
#pragma unroll
    for (int i = 0; i < 4; i++)
#pragma unroll
        for (int j = 0; j < 4; j++) acc2[i][j] = 0ull;

    for (int k0 = 0; k0 < K; k0 += 16) {
        // load X tile (128 x 16)
#pragma unroll
        for (int i = 0; i < 8; i++) {
            int lin = i * 256 + t;
            int r = lin >> 4, c = lin & 15;
            int gm = bm + r, gk = k0 + c;
            float v = 0.f;
            if (gk < K && gm < M) {
                if (useG) {
                    int pid = sPid[r];
                    if (gk < 3) {
                        int cr = gm >> gNsShift;
                        v = __fdiv_rn(__fsub_rn(gPts[(size_t)pid * 3 + gk],
                                                gCtr[(size_t)cr * 3 + gk]), gRad);
                    } else {
                        v = gFeats[(size_t)pid * gCF + (gk - 3)];
                    }
                } else {
                    v = X[(size_t)gm * K + gk];
                    if (useBn) v = fmaxf(0.f, (v - sMean[gk]) * sInv[gk]);
                }
            }
            As[c][r] = v;
        }
        // load W tile (64 x 16)
#pragma unroll
        for (int i = 0; i < 4; i++) {
            int lin = i * 256 + t;
            int r = lin >> 4, c = lin & 15;
            int gn = bn + r, gk = k0 + c;
            Bs[c][r] = (gk < K && gn < N) ? W[(size_t)gn * K + gk] : 0.f;
        }
        __syncthreads();
#pragma unroll
        for (int kk = 0; kk < 16; kk++) {
            ulonglong2 A0 = *reinterpret_cast<const ulonglong2*>(&As[kk][ty * 8]);
            ulonglong2 A1 = *reinterpret_cast<const ulonglong2*>(&As[kk][ty * 8 + 4]);
            float4 bv = *reinterpret_cast<const float4*>(&Bs[kk][tx * 4]);
            unsigned long long aP[4] = {A0.x, A0.y, A1.x, A1.y};
            unsigned long long bp[4];
            PACK_F32X2(bp[0], __float_as_uint(bv.x), __float_as_uint(bv.x));
            PACK_F32X2(bp[1], __float_as_uint(bv.y), __float_as_uint(bv.y));
            PACK_F32X2(bp[2], __float_as_uint(bv.z), __float_as_uint(bv.z));
            PACK_F32X2(bp[3], __float_as_uint(bv.w), __float_as_uint(bv.w));
#pragma unroll
            for (int ip = 0; ip < 4; ip++)
#pragma unroll
                for (int j = 0; j < 4; j++)
                    FMA_F32X2(acc2[ip][j], aP[ip], bp[j]);
        }
        __syncthreads();
    }

    // unpack accumulators
    float acc[8][4];
#pragma unroll
    for (int ip = 0; ip < 4; ip++)
#pragma unroll
        for (int j = 0; j < 4; j++) {
            unsigned lo, hi;
            UNPACK_F32X2(lo, hi, acc2[ip][j]);
            acc[2 * ip + 0][j] = __uint_as_float(lo);
            acc[2 * ip + 1][j] = __uint_as_float(hi);
        }

    // epilogue: store + optional per-column stats
    float colS[4] = {0.f, 0.f, 0.f, 0.f};
    float colQ[4] = {0.f, 0.f, 0.f, 0.f};
#pragma unroll
    for (int i = 0; i < 8; i++) {
        int gm = bm + ty * 8 + i;
        if (gm >= M) continue;
#pragma unroll
        for (int j = 0; j < 4; j++) {
            int gn = bn + tx * 4 + j;
            if (gn >= N) continue;
            float v = acc[i][j];
            Y[(size_t)gm * N + gn] = v;
            colS[j] += v;
            colQ[j] = fmaf(v, v, colQ[j]);
        }
    }

    if (outSum) {
#pragma unroll
        for (int j = 0; j < 4; j++) {
            colS[j] += __shfl_down_sync(0xffffffffu, colS[j], 16);
            colQ[j] += __shfl_down_sync(0xffffffffu, colQ[j], 16);
        }
        if (t < 64) { sSum[t] = 0.f; sSq[t] = 0.f; }
        __syncthreads();
        if ((t & 31) < 16) {
#pragma unroll
            for (int j = 0; j < 4; j++) {
                atomicAdd(&sSum[tx * 4 + j], colS[j]);
                atomicAdd(&sSq[tx * 4 + j], colQ[j]);
            }
        }
        __syncthreads();
        if (t < 64) {
            int gn = bn + t;
            if (gn < N) {
                atomicAdd(&outSum[gn], sSum[t]);
                atomicAdd(&outSq[gn], sSq[t]);
            }
        }
    }
}

// ---------------------------------------------------------------------------
// Small-M GEMM for the head (M <= 8): warp-per-column, X cached in smem.
// ---------------------------------------------------------------------------
__global__ __launch_bounds__(256) void gemm_small_kernel(
    const float* __restrict__ X, const float* __restrict__ W,
    const float* __restrict__ bias, float* __restrict__ Y,
    int M, int N, int K, int relu)
{
    __shared__ float sX[8 * 1152];
    for (int i = threadIdx.x; i < M * K; i += 256) sX[i] = X[i];
    __syncthreads();
    int warp = threadIdx.x >> 5, lane = threadIdx.x & 31;
    int n = blockIdx.x * 8 + warp;
    if (n >= N) return;
    float acc[8];
#pragma unroll
    for (int m = 0; m < 8; m++) acc[m] = 0.f;
    for (int k = lane; k < K; k += 32) {
        float wv = W[(size_t)n * K + k];
#pragma unroll
        for (int m = 0; m < 8; m++)
            acc[m] = fmaf(sX[m * K + k], wv, acc[m]);
    }
#pragma unroll
    for (int m = 0; m < 8; m++) {
#pragma unroll
        for (int o = 16; o > 0; o >>= 1)
            acc[m] += __shfl_down_sync(0xffffffffu, acc[m], o);
    }
    if (lane == 0) {
        for (int m = 0; m < M; m++) {
            float v = acc[m] + bias[n];
            if (relu) v = fmaxf(v, 0.f);
            Y[(size_t)m * N + n] = v;
        }
    }
}

// ---------------------------------------------------------------------------
// BN helpers
// ---------------------------------------------------------------------------
__global__ void bn_zero_kernel(float* s, float* q, int C)
{
    int i = blockIdx.x * blockDim.x + threadIdx.x;
    if (i < C) { s[i] = 0.f; q[i] = 0.f; }
}

__global__ void bn_col_kernel(float* __restrict__ X, int M, int C, int relu)
{
    int c = blockIdx.x * blockDim.x + threadIdx.x;
    if (c >= C) return;
    float s = 0.f, q = 0.f;
    for (int m = 0; m < M; m++) {
        float v = X[(size_t)m * C + c];
        s += v;
        q = fmaf(v, v, q);
    }
    float mean = s / (float)M;
    float var = fmaxf(q / (float)M - mean * mean, 0.f);
    float inv = 1.f / sqrtf(var + BN_EPS);
    for (int m = 0; m < M; m++) {
        float v = (X[(size_t)m * C + c] - mean) * inv;
        if (relu) v = fmaxf(v, 0.f);
        X[(size_t)m * C + c] = v;
    }
}

// ---------------------------------------------------------------------------
// Max pool over group axis + BN(from raw sums) + ReLU
// ---------------------------------------------------------------------------
__global__ void maxpool_bn_kernel(const float* __restrict__ X, float* __restrict__ Y,
                                  int R, int ns, int C,
                                  const float* __restrict__ gsum,
                                  const float* __restrict__ gsq, float invM)
{
    unsigned total = (unsigned)R * C;
    unsigned stride = gridDim.x * blockDim.x;
    for (unsigned e = blockIdx.x * blockDim.x + threadIdx.x; e < total; e += stride) {
        int r = e / C;
        int c = e % C;
        const float* p = X + ((size_t)r * ns) * C + c;
        float m = -3.402823466e38f;
        for (int j = 0; j < ns; j++) m = fmaxf(m, p[(size_t)j * C]);
        float mean = gsum[c] * invM;
        float var = fmaxf(gsq[c] * invM - mean * mean, 0.f);
        float inv = 1.f / sqrtf(var + BN_EPS);
        Y[e] = fmaxf(0.f, (m - mean) * inv);
    }
}

// ---------------------------------------------------------------------------
// FPS1: one block per batch, 512 threads, padded to 20480 pts (40/thread).
// xy pairs in smem as (x0,x1,y0,y1); z packed in regs; f32x2 distance math.
// Padding points have dist=-1 so they can never win the argmax.
// ---------------------------------------------------------------------------
__global__ void __launch_bounds__(512) fps1_kernel(
    const float* __restrict__ xyz, int npoint,
    int* __restrict__ idx_out, float* __restrict__ newxyz)
{
    extern __shared__ float4 sxy[];   // [10240] pair -> (x0, x1, y0, y1)
    const int N = 20000;
    const int b = blockIdx.x;
    const int t = threadIdx.x;
    const float* P = xyz + (size_t)b * N * 3;

    __shared__ float s_v[16];
    __shared__ int   s_i[16];
    __shared__ float s_far[3];

    for (int i = t; i < 10240; i += 512) {
        int p0 = 2 * i, p1 = 2 * i + 1;
        float x0 = 0.f, y0 = 0.f, x1 = 0.f, y1 = 0.f;
        if (p0 < N) { x0 = P[p0 * 3]; y0 = P[p0 * 3 + 1]; }
        if (p1 < N) { x1 = P[p1 * 3]; y1 = P[p1 * 3 + 1]; }
        sxy[i] = make_float4(x0, x1, y0, y1);
    }
    unsigned long long zz[20];
    float dist[40];
#pragma unroll
    for (int k = 0; k < 20; k++) {
        int p0 = 2 * (t + k * 512), p1 = p0 + 1;
        float z0 = (p0 < N) ? P[p0 * 3 + 2] : 0.f;
        float z1 = (p1 < N) ? P[p1 * 3 + 2] : 0.f;
        PACK_F32X2(zz[k], __float_as_uint(z0), __float_as_uint(z1));
        dist[2 * k]     = (p0 < N) ? 1e10f : -1.f;
        dist[2 * k + 1] = (p1 < N) ? 1e10f : -1.f;
    }
    if (t == 0) {
        idx_out[b * npoint] = 0;
        float fx = P[0], fy = P[1], fz = P[2];
        newxyz[(size_t)b * npoint * 3 + 0] = fx;
        newxyz[(size_t)b * npoint * 3 + 1] = fy;
        newxyz[(size_t)b * npoint * 3 + 2] = fz;
        s_far[0] = fx; s_far[1] = fy; s_far[2] = fz;
    }
    __syncthreads();

    for (int it = 1; it < npoint; it++) {
        // pre-negate center; x + (-fx) is IEEE-identical to x - fx
        unsigned long long nfx2, nfy2, nfz2;
        {
            unsigned nx = __float_as_uint(-s_far[0]);
            unsigned ny = __float_as_uint(-s_far[1]);
            unsigned nz = __float_as_uint(-s_far[2]);
            PACK_F32X2(nfx2, nx, nx);
            PACK_F32X2(nfy2, ny, ny);
            PACK_F32X2(nfz2, nz, nz);
        }
        float best = -1.f;
        int bi = 0x7fffffff;
#pragma unroll
        for (int k = 0; k < 20; k++) {
            float4 q = sxy[t + k * 512];
            unsigned long long xx, yy;
            PACK_F32X2(xx, __float_as_uint(q.x), __float_as_uint(q.y));
            PACK_F32X2(yy, __float_as_uint(q.z), __float_as_uint(q.w));
            unsigned long long dx2, dy2, dz2, xs, ys, zs, s01, d2;
            ADD_F32X2(dx2, xx, nfx2);
            ADD_F32X2(dy2, yy, nfy2);
            ADD_F32X2(dz2, zz[k], nfz2);
            MUL_F32X2(xs, dx2, dx2);
            MUL_F32X2(ys, dy2, dy2);
            MUL_F32X2(zs, dz2, dz2);
            ADD_F32X2(s01, xs, ys);
            ADD_F32X2(d2, s01, zs);
            unsigned ulo, uhi;
            UNPACK_F32X2(ulo, uhi, d2);
            float n0 = fminf(dist[2 * k], __uint_as_float(ulo));
            dist[2 * k] = n0;
            if (n0 > best) { best = n0; bi = 2 * (t + k * 512); }
            float n1 = fminf(dist[2 * k + 1], __uint_as_float(uhi));
            dist[2 * k + 1] = n1;
            if (n1 > best) { best = n1; bi = 2 * (t + k * 512) + 1; }
        }
#pragma unroll
        for (int o = 16; o > 0; o >>= 1) {
            float ov = __shfl_down_sync(0xffffffffu, best, o);
            int   oi = __shfl_down_sync(0xffffffffu, bi, o);
            if (ov > best || (ov == best && oi < bi)) { best = ov; bi = oi; }
        }
        if ((t & 31) == 0) { s_v[t >> 5] = best; s_i[t >> 5] = bi; }
        __syncthreads();
        if (t < 32) {
            best = (t < 16) ? s_v[t] : -1.f;
            bi   = (t < 16) ? s_i[t] : 0x7fffffff;
#pragma unroll
            for (int o = 8; o > 0; o >>= 1) {
                float ov = __shfl_down_sync(0xffffffffu, best, o);
                int   oi = __shfl_down_sync(0xffffffffu, bi, o);
                if (ov > best || (ov == best && oi < bi)) { best = ov; bi = oi; }
            }
            if (t == 0) {
                float4 q = sxy[bi >> 1];
                float fx2 = (bi & 1) ? q.y : q.x;
                float fy2 = (bi & 1) ? q.w : q.z;
                float fz2 = P[bi * 3 + 2];
                idx_out[b * npoint + it] = bi;
                newxyz[((size_t)b * npoint + it) * 3 + 0] = fx2;
                newxyz[((size_t)b * npoint + it) * 3 + 1] = fy2;
                newxyz[((size_t)b * npoint + it) * 3 + 2] = fz2;
                s_far[0] = fx2; s_far[1] = fy2; s_far[2] = fz2;
            }
        }
        __syncthreads();
    }
}

// ---------------------------------------------------------------------------
// FPS2: one warp per batch, all pts in registers (N=512), no block syncs.
// ---------------------------------------------------------------------------
__global__ void __launch_bounds__(32) fps_warp_kernel(
    const float* __restrict__ xyz, int N, int npoint,
    int* __restrict__ idx_out, float* __restrict__ newxyz)
{
    const int b = blockIdx.x;
    const int lane = threadIdx.x;
    const float* P = xyz + (size_t)b * N * 3;

    float x[16], y[16], z[16], dist[16];
#pragma unroll
    for (int k = 0; k < 16; k++) {
        int p = lane + k * 32;
        x[k] = P[p * 3 + 0];
        y[k] = P[p * 3 + 1];
        z[k] = P[p * 3 + 2];
        dist[k] = 1e10f;
    }
    float fx = P[0], fy = P[1], fz = P[2];
    if (lane == 0) {
        idx_out[b * npoint] = 0;
        newxyz[(size_t)b * npoint * 3 + 0] = fx;
        newxyz[(size_t)b * npoint * 3 + 1] = fy;
        newxyz[(size_t)b * npoint * 3 + 2] = fz;
    }
    for (int it = 1; it < npoint; it++) {
        float best = -1.f;
        int bi = 0x7fffffff;
#pragma unroll
        for (int k = 0; k < 16; k++) {
            float dx = __fsub_rn(x[k], fx);
            float dy = __fsub_rn(y[k], fy);
            float dz = __fsub_rn(z[k], fz);
            float d = __fadd_rn(__fadd_rn(__fmul_rn(dx, dx), __fmul_rn(dy, dy)),
                                __fmul_rn(dz, dz));
            float nd = fminf(dist[k], d);
            dist[k] = nd;
            if (nd > best) { best = nd; bi = lane + k * 32; }
        }
#pragma unroll
        for (int o = 16; o > 0; o >>= 1) {
            float ov = __shfl_xor_sync(0xffffffffu, best, o);
            int   oi = __shfl_xor_sync(0xffffffffu, bi, o);
            if (ov > best || (ov == best && oi < bi)) { best = ov; bi = oi; }
        }
        fx = P[bi * 3 + 0];
        fy = P[bi * 3 + 1];
        fz = P[bi * 3 + 2];
        if (lane == 0) {
            idx_out[b * npoint + it] = bi;
            newxyz[((size_t)b * npoint + it) * 3 + 0] = fx;
            newxyz[((size_t)b * npoint + it) * 3 + 1] = fy;
            newxyz[((size_t)b * npoint + it) * 3 + 2] = fz;
        }
    }
}

// ---------------------------------------------------------------------------
// Ball query — one warp per center; MLP-batched scan of 256-point superchunks.
// ---------------------------------------------------------------------------
__global__ __launch_bounds__(256) void ballquery_kernel(
    const float* __restrict__ centers, const float* __restrict__ pts,
    int B, int S, int N, float r2, int nsample, int* __restrict__ out)
{
    int wg = (blockIdx.x * blockDim.x + threadIdx.x) >> 5;
    int lane = threadIdx.x & 31;
    if (wg >= B * S) return;
    int b = wg / S;
    const float* P = pts + (size_t)b * N * 3;
    float cx = centers[(size_t)wg * 3 + 0];
    float cy = centers[(size_t)wg * 3 + 1];
    float cz = centers[(size_t)wg * 3 + 2];
    int* o = out + (size_t)wg * nsample;

    int count = 0;
    int first = -1;
    for (int base = 0; base < N && count < nsample; base += 256) {
        bool ins[8];
#pragma unroll
        for (int j = 0; j < 8; j++) {
            int p = base + j * 32 + lane;
            bool inside = false;
            if (p < N) {
                float dx = __fsub_rn(cx, P[p * 3 + 0]);
                float dy = __fsub_rn(cy, P[p * 3 + 1]);
                float dz = __fsub_rn(cz, P[p * 3 + 2]);
                float d2 = __fadd_rn(__fadd_rn(__fmul_rn(dx, dx), __fmul_rn(dy, dy)),
                                     __fmul_rn(dz, dz));
                inside = d2 < r2;
            }
            ins[j] = inside;
        }
#pragma unroll
        for (int j = 0; j < 8; j++) {
            unsigned m = __ballot_sync(0xffffffffu, ins[j]);
            if (first < 0 && m) first = base + j * 32 + __ffs(m) - 1;
            if (ins[j]) {
                int pos = count + __popc(m & ((1u << lane) - 1u));
                if (pos < nsample) o[pos] = base + j * 32 + lane;
            }
            count += __popc(m);
        }
    }
    int start = count < nsample ? count : nsample;
    for (int k = start + lane; k < nsample; k += 32) o[k] = first;
}

// ---------------------------------------------------------------------------
// Concat kernels
// ---------------------------------------------------------------------------
__global__ void concat_sa3_kernel(const float* __restrict__ xyz2,
                                  const float* __restrict__ f2,
                                  float* __restrict__ out, int R, int CF)
{
    int C = 3 + CF;
    unsigned total = (unsigned)R * C;
    unsigned stride = gridDim.x * blockDim.x;
    for (unsigned e = blockIdx.x * blockDim.x + threadIdx.x; e < total; e += stride) {
        int r = e / C;
        int c = e % C;
        out[e] = (c < 3) ? xyz2[(size_t)r * 3 + c] : f2[(size_t)r * CF + (c - 3)];
    }
}

__global__ void concat_comb_kernel(const float* __restrict__ gf,
                                   const float* __restrict__ of,
                                   float* __restrict__ out, int B, int C1, int C2)
{
    int C = C1 + C2;
    unsigned total = (unsigned)B * C;
    unsigned stride = gridDim.x * blockDim.x;
    for (unsigned e = blockIdx.x * blockDim.x + threadIdx.x; e < total; e += stride) {
        int b = e / C;
        int c = e % C;
        out[e] = (c < C1) ? gf[(size_t)b * C1 + c] : of[(size_t)b * C2 + (c - C1)];
    }
}

// ---------------------------------------------------------------------------
// Host orchestration
// ---------------------------------------------------------------------------
static inline int cdiv(long a, long b) { return (int)((a + b - 1) / b); }
static int ew_blocks(long total)
{
    int b = cdiv(total, 256);
    return b > 4096 ? 4096 : b;
}

struct GatherArgs {
    const int* idx; const float* pts; const float* ctr; const float* feats;
    int npts, bShift, nsShift, cf; float rad;
};

static void launch_tile(const float* X, const float* W, float* Y,
                        int M, int N, int K,
                        const float* inSum, const float* inSq, float invMin,
                        float* outSum, float* outSq,
                        const GatherArgs* ga)
{
    dim3 grid(cdiv(N, 64), cdiv(M, 128));
    if (ga) {
        gemm_tile_kernel<<<grid, 256>>>(X, W, Y, M, N, K,
            inSum, inSq, invMin, outSum, outSq,
            ga->idx, ga->pts, ga->ctr, ga->feats,
            ga->npts, ga->bShift, ga->nsShift, ga->cf, ga->rad);
    } else {
        gemm_tile_kernel<<<grid, 256>>>(X, W, Y, M, N, K,
            inSum, inSq, invMin, outSum, outSq,
            nullptr, nullptr, nullptr, nullptr, 0, 0, 0, 0, 0.f);
    }
}

extern "C" void kernel_launch(void* const* d_in, const int* in_sizes, int n_in,
                              void* d_out, int out_size)
{
    (void)in_sizes; (void)n_in; (void)out_size;
    const float* obj   = (const float*)d_in[0];
    const float* grip  = (const float*)d_in[1];
    const float* sa1w0 = (const float*)d_in[2];
    const float* sa1w1 = (const float*)d_in[3];
    const float* sa1w2 = (const float*)d_in[4];
    const float* sa2w0 = (const float*)d_in[5];
    const float* sa2w1 = (const float*)d_in[6];
    const float* sa2w2 = (const float*)d_in[7];
    const float* sa3w0 = (const float*)d_in[8];
    const float* sa3w1 = (const float*)d_in[9];
    const float* sa3w2 = (const float*)d_in[10];
    const float* gew0  = (const float*)d_in[11];
    const float* gew1  = (const float*)d_in[12];
    const float* gew2  = (const float*)d_in[13];
    const float* hw0   = (const float*)d_in[14];
    const float* hb0   = (const float*)d_in[15];
    const float* hw1   = (const float*)d_in[16];
    const float* hb1   = (const float*)d_in[17];
    const float* hw2   = (const float*)d_in[18];
    const float* hb2   = (const float*)d_in[19];

    float *bufA, *bufB, *f1, *f2, *sa3in, *gfeat, *objf, *comb, *h0, *h1;
    float *xyz1, *xyz2, *bsum, *bsq;
    int *fps1, *fps2, *bq1, *bq2;
    cudaGetSymbolAddress((void**)&bufA,  g_bufA);
    cudaGetSymbolAddress((void**)&bufB,  g_bufB);
    cudaGetSymbolAddress((void**)&f1,    g_f1);
    cudaGetSymbolAddress((void**)&f2,    g_f2);
    cudaGetSymbolAddress((void**)&sa3in, g_sa3in);
    cudaGetSymbolAddress((void**)&gfeat, g_gfeat);
    cudaGetSymbolAddress((void**)&objf,  g_objfeat);
    cudaGetSymbolAddress((void**)&comb,  g_comb);
    cudaGetSymbolAddress((void**)&h0,    g_h0);
    cudaGetSymbolAddress((void**)&h1,    g_h1);
    cudaGetSymbolAddress((void**)&xyz1,  g_xyz1);
    cudaGetSymbolAddress((void**)&xyz2,  g_xyz2);
    cudaGetSymbolAddress((void**)&fps1,  g_fps1);
    cudaGetSymbolAddress((void**)&fps2,  g_fps2);
    cudaGetSymbolAddress((void**)&bq1,   g_bq1);
    cudaGetSymbolAddress((void**)&bq2,   g_bq2);
    cudaGetSymbolAddress((void**)&bsum,  g_bnsum);
    cudaGetSymbolAddress((void**)&bsq,   g_bnsq);

    const int B = 8, N0 = 20000, G = 512;
    const int S1 = 512, NS1 = 32, S2 = 128, NS2 = 64;
    const float r2_1 = (float)(0.2 * 0.2);
    const float r2_2 = (float)(0.4 * 0.4);

    // per-layer stat region offsets (channels)
    const int oGE0 = 0, oGE1 = 64, oGE2 = 192;           // 64,128,128
    const int oS10 = 320, oS11 = 384, oS12 = 448;        // 64,64,128
    const int oS20 = 576, oS21 = 704, oS22 = 832;        // 128,128,256
    const int oS30 = 1088, oS31 = 1344, oS32 = 1856;     // 256,512,1024

    bn_zero_kernel<<<cdiv(4096, 256), 256>>>(bsum, bsq, 4096);

    // ---------------- FPS ----------------
    cudaFuncSetAttribute(fps1_kernel, cudaFuncAttributeMaxDynamicSharedMemorySize,
                         10240 * (int)sizeof(float4));
    fps1_kernel<<<B, 512, 10240 * sizeof(float4)>>>(obj, S1, fps1, xyz1);
    fps_warp_kernel<<<B, 32>>>(xyz1, S1, S2, fps2, xyz2);

    // ---------------- ball queries ----------------
    ballquery_kernel<<<cdiv((long)B * S1 * 32, 256), 256>>>(xyz1, obj, B, S1, N0,
                                                            r2_1, NS1, bq1);
    ballquery_kernel<<<cdiv((long)B * S2 * 32, 256), 256>>>(xyz2, xyz1, B, S2, S1,
                                                            r2_2, NS2, bq2);

    // ---------------- gripper encoder ----------------
    {
        int M = B * G;  // 4096
        float iM = 1.f / (float)M;
        launch_tile(grip, gew0, bufB, M, 64, 3,
                    nullptr, nullptr, 0.f, bsum + oGE0, bsq + oGE0, nullptr);
        launch_tile(bufB, gew1, bufA, M, 128, 64,
                    bsum + oGE0, bsq + oGE0, iM, bsum + oGE1, bsq + oGE1, nullptr);
        launch_tile(bufA, gew2, bufB, M, 128, 128,
                    bsum + oGE1, bsq + oGE1, iM, bsum + oGE2, bsq + oGE2, nullptr);
        maxpool_bn_kernel<<<ew_blocks((long)B * 128), 256>>>(bufB, gfeat, B, G, 128,
                                                             bsum + oGE2, bsq + oGE2, iM);
    }

    // ---------------- SA1 ----------------
    {
        int M = B * S1 * NS1;  // 131072
        float iM = 1.f / (float)M;
        GatherArgs ga = {bq1, obj, xyz1, nullptr, N0, 14, 5, 0, 0.2f};
        launch_tile(nullptr, sa1w0, bufB, M, 64, 3,
                    nullptr, nullptr, 0.f, bsum + oS10, bsq + oS10, &ga);
        launch_tile(bufB, sa1w1, bufA, M, 64, 64,
                    bsum + oS10, bsq + oS10, iM, bsum + oS11, bsq + oS11, nullptr);
        launch_tile(bufA, sa1w2, bufB, M, 128, 64,
                    bsum + oS11, bsq + oS11, iM, bsum + oS12, bsq + oS12, nullptr);
        maxpool_bn_kernel<<<ew_blocks((long)B * S1 * 128), 256>>>(
            bufB, f1, B * S1, NS1, 128, bsum + oS12, bsq + oS12, iM);
    }

    // ---------------- SA2 ----------------
    {
        int M = B * S2 * NS2;  // 65536
        float iM = 1.f / (float)M;
        GatherArgs ga = {bq2, xyz1, xyz2, f1, S1, 13, 6, 128, 0.4f};
        launch_tile(nullptr, sa2w0, bufB, M, 128, 131,
                    nullptr, nullptr, 0.f, bsum + oS20, bsq + oS20, &ga);
        launch_tile(bufB, sa2w1, bufA, M, 128, 128,
                    bsum + oS20, bsq + oS20, iM, bsum + oS21, bsq + oS21, nullptr);
        launch_tile(bufA, sa2w2, bufB, M, 256, 128,
                    bsum + oS21, bsq + oS21, iM, bsum + oS22, bsq + oS22, nullptr);
        maxpool_bn_kernel<<<ew_blocks((long)B * S2 * 256), 256>>>(
            bufB, f2, B * S2, NS2, 256, bsum + oS22, bsq + oS22, iM);
    }

    // ---------------- SA3 (group_all) ----------------
    {
        int M = B * S2;  // 1024
        float iM = 1.f / (float)M;
        concat_sa3_kernel<<<ew_blocks((long)M * 259), 256>>>(xyz2, f2, sa3in, M, 256);
        launch_tile(sa3in, sa3w0, bufA, M, 256, 259,
                    nullptr, nullptr, 0.f, bsum + oS30, bsq + oS30, nullptr);
        launch_tile(bufA, sa3w1, bufB, M, 512, 256,
                    bsum + oS30, bsq + oS30, iM, bsum + oS31, bsq + oS31, nullptr);
        launch_tile(bufB, sa3w2, bufA, M, 1024, 512,
                    bsum + oS31, bsq + oS31, iM, bsum + oS32, bsq + oS32, nullptr);
        maxpool_bn_kernel<<<ew_blocks((long)B * 1024), 256>>>(
            bufA, objf, B, S2, 1024, bsum + oS32, bsq + oS32, iM);
    }

    // ---------------- head ----------------
    {
        concat_comb_kernel<<<ew_blocks((long)B * 1152), 256>>>(gfeat, objf, comb,
                                                               B, 128, 1024);
        bn_col_kernel<<<cdiv(1152, 256), 256>>>(comb, B, 1152, 0);
        gemm_small_kernel<<<cdiv(512, 8), 256>>>(comb, hw0, hb0, h0, B, 512, 1152, 0);
        bn_col_kernel<<<cdiv(512, 256), 256>>>(h0, B, 512, 1);
        gemm_small_kernel<<<cdiv(256, 8), 256>>>(h0, hw1, hb1, h1, B, 256, 512, 0);
        bn_col_kernel<<<cdiv(256, 256), 256>>>(h1, B, 256, 1);
        gemm_small_kernel<<<1, 256>>>(h1, hw2, hb2, (float*)d_out, B, 1, 256, 1);
    }
}

// round 10
// speedup vs baseline: 1.7221x; 1.1705x over previous
#include <cuda_runtime.h>
#include <math.h>

#define BN_EPS 1e-5f

// ---- packed fp32x2 helpers (sm_103a dual-FP32 pipe) ----
#define PACK_F32X2(out, lo, hi) \
    asm("mov.b64 %0, {%1, %2};" : "=l"(out) : "r"(lo), "r"(hi))
#define UNPACK_F32X2(lo, hi, in) \
    asm("mov.b64 {%0, %1}, %2;" : "=r"(lo), "=r"(hi) : "l"(in))
#define ADD_F32X2(out, a, b) \
    asm("add.rn.f32x2 %0, %1, %2;" : "=l"(out) : "l"(a), "l"(b))
#define MUL_F32X2(out, a, b) \
    asm("mul.rn.f32x2 %0, %1, %2;" : "=l"(out) : "l"(a), "l"(b))
#define FMA_F32X2(d, a, b) \
    asm("fma.rn.f32x2 %0, %1, %2, %0;" : "+l"(d) : "l"(a), "l"(b))

__device__ __forceinline__ unsigned ordflip(float f)
{
    unsigned u = __float_as_uint(f);
    return (u & 0x80000000u) ? ~u : (u | 0x80000000u);
}
__device__ __forceinline__ float ordunflip(unsigned u)
{
    return __uint_as_float((u & 0x80000000u) ? (u ^ 0x80000000u) : ~u);
}

// ---------------------------------------------------------------------------
// Static device scratch
// ---------------------------------------------------------------------------
__device__ float g_bufA[131072 * 128];
__device__ float g_bufB[131072 * 128];
__device__ float g_praw[4096 * 128];      // pooled raw max (largest: SA1 4096x128)
__device__ float g_f1[8 * 512 * 128];
__device__ float g_f2[8 * 128 * 256];
__device__ float g_sa3in[1024 * 259];
__device__ float g_gfeat[8 * 128];
__device__ float g_objfeat[8 * 1024];
__device__ float g_comb[8 * 1152];
__device__ float g_h0[8 * 512];
__device__ float g_h1[8 * 256];
__device__ float g_xyz1[8 * 512 * 3];
__device__ float g_xyz2[8 * 128 * 3];
__device__ int   g_fps1[8 * 512];
__device__ int   g_fps2[8 * 128];
__device__ int   g_bq1[8 * 512 * 32];
__device__ int   g_bq2[8 * 128 * 64];
__device__ float g_bnsum[4096];
__device__ float g_bnsq[4096];

// ---------------------------------------------------------------------------
// Tiled GEMM:  Y[M,N] = f(X)[M,K] * W[N,K]^T
//  BM=128, BN=64, BK=16, 256 threads, 8x4 microtile, f32x2 FMA,
//  double-buffered smem with register staging.
//  Input modes: gather (ball-query fusion) / bn (relu((x-mean)*inv)) / plain.
//  Epilogue: per-column sum/sumsq stats; optional fused group-maxpool
//  (poolY != null: raw group max written, Y store skipped when Y == null).
// ---------------------------------------------------------------------------
__global__ __launch_bounds__(256, 2) void gemm_tile_kernel(
    const float* __restrict__ X, const float* __restrict__ W,
    float* __restrict__ Y, int M, int N, int K,
    const float* __restrict__ inSum, const float* __restrict__ inSq, float invMin,
    float* __restrict__ outSum, float* __restrict__ outSq,
    const int* __restrict__ gIdx, const float* __restrict__ gPts,
    const float* __restrict__ gCtr, const float* __restrict__ gFeats,
    int gNpts, int gBShift, int gNsShift, int gCF, float gRad,
    float* __restrict__ poolY, int poolShift)
{
    __shared__ __align__(16) float As[2][16][132];
    __shared__ __align__(16) float Bs[2][16][68];
    __shared__ float sMean[512];
    __shared__ float sInv[512];
    __shared__ int   sPid[128];
    __shared__ float sSum[64];
    __shared__ float sSq[64];
    __shared__ unsigned sPoolU[256];

    const int bm = blockIdx.y * 128;
    const int bn = blockIdx.x * 64;
    const int t  = threadIdx.x;
    const int ty = t >> 4;   // 0..15
    const int tx = t & 15;   // 0..15

    const bool useBn = (inSum != nullptr);
    const bool useG  = (gIdx != nullptr);

    if (useBn) {
        for (int k = t; k < K; k += 256) {
            float m = inSum[k] * invMin;
            float var = fmaxf(inSq[k] * invMin - m * m, 0.f);
            sMean[k] = m;
            sInv[k] = 1.f / sqrtf(var + BN_EPS);
        }
    }
    if (useG && t < 128) {
        int g = bm + t;
        int pid = 0;
        if (g < M) pid = (g >> gBShift) * gNpts + gIdx[g];
        sPid[t] = pid;
    }
    if (useBn || useG) __syncthreads();

    // packed accumulators: acc2[ip][j] = (acc[2ip][j], acc[2ip+1][j])
    unsigned long long acc2[4][4];
#pragma unroll
    for (int i = 0; i < 4; i++)
#pragma unroll
        for (int j = 0; j < 4; j++) acc2[i][j] = 0ull;

    float aReg[8];
    float bReg[4];

    auto loadA = [&](int k0) {
#pragma unroll
        for (int i = 0; i < 8; i++) {
            int lin = i * 256 + t;
            int r = lin >> 4, c = lin & 15;
            int gm = bm + r, gk = k0 + c;
            float v = 0.f;
            if (gk < K && gm < M) {
                if (useG) {
                    int pid = sPid[r];
                    if (gk < 3) {
                        int cr = gm >> gNsShift;
                        v = __fdiv_rn(__fsub_rn(gPts[(size_t)pid * 3 + gk],
                                                gCtr[(size_t)cr * 3 + gk]), gRad);
                    } else {
                        v = gFeats[(size_t)pid * gCF + (gk - 3)];
                    }
                } else {
                    v = X[(size_t)gm * K + gk];
                    if (useBn) v = fmaxf(0.f, (v - sMean[gk]) * sInv[gk]);
                }
            }
            aReg[i] = v;
        }
    };
    auto loadB = [&](int k0) {
#pragma unroll
        for (int i = 0; i < 4; i++) {
            int lin = i * 256 + t;
            int r = lin >> 4, c = lin & 15;
            int gn = bn + r, gk = k0 + c;
            bReg[i] = (gk < K && gn < N) ? W[(size_t)gn * K + gk] : 0.f;
        }
    };
    auto storeS = [&](int buf) {
#pragma unroll
        for (int i = 0; i < 8; i++) {
            int lin = i * 256 + t;
            As[buf][lin & 15][lin >> 4] = aReg[i];
        }
#pragma unroll
        for (int i = 0; i < 4; i++) {
            int lin = i * 256 + t;
            Bs[buf][lin & 15][lin >> 4] = bReg[i];
        }
    };
    auto compute = [&](int buf) {
#pragma unroll
        for (int kk = 0; kk < 16; kk++) {
            ulonglong2 A0 = *reinterpret_cast<const ulonglong2*>(&As[buf][kk][ty * 8]);
            ulonglong2 A1 = *reinterpret_cast<const ulonglong2*>(&As[buf][kk][ty * 8 + 4]);
            float4 bv = *reinterpret_cast<const float4*>(&Bs[buf][kk][tx * 4]);
            unsigned long long aP[4] = {A0.x, A0.y, A1.x, A1.y};
            unsigned long long bp[4];
            PACK_F32X2(bp[0], __float_as_uint(bv.x), __float_as_uint(bv.x));
            PACK_F32X2(bp[1], __float_as_uint(bv.y), __float_as_uint(bv.y));
            PACK_F32X2(bp[2], __float_as_uint(bv.z), __float_as_uint(bv.z));
            PACK_F32X2(bp[3], __float_as_uint(bv.w), __float_as_uint(bv.w));
#pragma unroll
            for (int ip = 0; ip < 4; ip++)
#pragma unroll
                for (int j = 0; j < 4; j++)
                    FMA_F32X2(acc2[ip][j], aP[ip], bp[j]);
        }
    };

    const int nk = (K + 15) / 16;
    loadA(0); loadB(0);
    storeS(0);
    __syncthreads();
    for (int kt = 1; kt < nk; kt++) {
        loadA(kt * 16); loadB(kt * 16);
        compute((kt - 1) & 1);
        storeS(kt & 1);
        __syncthreads();
    }
    compute((nk - 1) & 1);

    // unpack accumulators
    float acc[8][4];
#pragma unroll
    for (int ip = 0; ip < 4; ip++)
#pragma unroll
        for (int j = 0; j < 4; j++) {
            unsigned lo, hi;
            UNPACK_F32X2(lo, hi, acc2[ip][j]);
            acc[2 * ip + 0][j] = __uint_as_float(lo);
            acc[2 * ip + 1][j] = __uint_as_float(hi);
        }

    // per-column stats
    float colS[4] = {0.f, 0.f, 0.f, 0.f};
    float colQ[4] = {0.f, 0.f, 0.f, 0.f};
#pragma unroll
    for (int i = 0; i < 8; i++) {
        int gm = bm + ty * 8 + i;
        if (gm >= M) continue;
#pragma unroll
        for (int j = 0; j < 4; j++) {
            int gn = bn + tx * 4 + j;
            if (gn >= N) continue;
            float v = acc[i][j];
            colS[j] += v;
            colQ[j] = fmaf(v, v, colQ[j]);
        }
    }

    // optional full store
    if (Y) {
#pragma unroll
        for (int i = 0; i < 8; i++) {
            int gm = bm + ty * 8 + i;
            if (gm >= M) continue;
#pragma unroll
            for (int j = 0; j < 4; j++) {
                int gn = bn + tx * 4 + j;
                if (gn >= N) continue;
                Y[(size_t)gm * N + gn] = acc[i][j];
            }
        }
    }

    // optional fused group-maxpool (groups of 2^poolShift rows; group fits block)
    if (poolY) {
        for (int i = t; i < 256; i += 256) sPoolU[i] = 0u;
        __syncthreads();
        int g = (ty * 8) >> poolShift;
#pragma unroll
        for (int j = 0; j < 4; j++) {
            float m8 = acc[0][j];
#pragma unroll
            for (int i = 1; i < 8; i++) m8 = fmaxf(m8, acc[i][j]);
            atomicMax(&sPoolU[g * 64 + tx * 4 + j], ordflip(m8));
        }
        __syncthreads();
        int nG = 128 >> poolShift;
        for (int idx = t; idx < nG * 64; idx += 256) {
            int gg = idx >> 6, c = idx & 63;
            int grow = (bm >> poolShift) + gg;
            poolY[(size_t)grow * N + bn + c] = ordunflip(sPoolU[idx]);
        }
    }

    if (outSum) {
#pragma unroll
        for (int j = 0; j < 4; j++) {
            colS[j] += __shfl_down_sync(0xffffffffu, colS[j], 16);
            colQ[j] += __shfl_down_sync(0xffffffffu, colQ[j], 16);
        }
        if (t < 64) { sSum[t] = 0.f; sSq[t] = 0.f; }
        __syncthreads();
        if ((t & 31) < 16) {
#pragma unroll
            for (int j = 0; j < 4; j++) {
                atomicAdd(&sSum[tx * 4 + j], colS[j]);
                atomicAdd(&sSq[tx * 4 + j], colQ[j]);
            }
        }
        __syncthreads();
        if (t < 64) {
            int gn = bn + t;
            if (gn < N) {
                atomicAdd(&outSum[gn], sSum[t]);
                atomicAdd(&outSq[gn], sSq[t]);
            }
        }
    }
}

// ---------------------------------------------------------------------------
// BN+ReLU normalize of pooled raw max (stats from raw sums)
// ---------------------------------------------------------------------------
__global__ void poolnorm_kernel(const float* __restrict__ raw, float* __restrict__ out,
                                unsigned total, int C,
                                const float* __restrict__ gsum,
                                const float* __restrict__ gsq, float invM)
{
    unsigned stride = gridDim.x * blockDim.x;
    for (unsigned e = blockIdx.x * blockDim.x + threadIdx.x; e < total; e += stride) {
        int c = e % C;
        float mean = gsum[c] * invM;
        float var = fmaxf(gsq[c] * invM - mean * mean, 0.f);
        float inv = 1.f / sqrtf(var + BN_EPS);
        out[e] = fmaxf(0.f, (raw[e] - mean) * inv);
    }
}

// ---------------------------------------------------------------------------
// Small-M GEMM for the head (M <= 8): warp-per-column, X cached in smem.
// ---------------------------------------------------------------------------
__global__ __launch_bounds__(256) void gemm_small_kernel(
    const float* __restrict__ X, const float* __restrict__ W,
    const float* __restrict__ bias, float* __restrict__ Y,
    int M, int N, int K, int relu)
{
    __shared__ float sX[8 * 1152];
    for (int i = threadIdx.x; i < M * K; i += 256) sX[i] = X[i];
    __syncthreads();
    int warp = threadIdx.x >> 5, lane = threadIdx.x & 31;
    int n = blockIdx.x * 8 + warp;
    if (n >= N) return;
    float acc[8];
#pragma unroll
    for (int m = 0; m < 8; m++) acc[m] = 0.f;
    for (int k = lane; k < K; k += 32) {
        float wv = W[(size_t)n * K + k];
#pragma unroll
        for (int m = 0; m < 8; m++)
            acc[m] = fmaf(sX[m * K + k], wv, acc[m]);
    }
#pragma unroll
    for (int m = 0; m < 8; m++) {
#pragma unroll
        for (int o = 16; o > 0; o >>= 1)
            acc[m] += __shfl_down_sync(0xffffffffu, acc[m], o);
    }
    if (lane == 0) {
        for (int m = 0; m < M; m++) {
            float v = acc[m] + bias[n];
            if (relu) v = fmaxf(v, 0.f);
            Y[(size_t)m * N + n] = v;
        }
    }
}

// ---------------------------------------------------------------------------
// BN helpers
// ---------------------------------------------------------------------------
__global__ void bn_zero_kernel(float* s, float* q, int C)
{
    int i = blockIdx.x * blockDim.x + threadIdx.x;
    if (i < C) { s[i] = 0.f; q[i] = 0.f; }
}

__global__ void bn_col_kernel(float* __restrict__ X, int M, int C, int relu)
{
    int c = blockIdx.x * blockDim.x + threadIdx.x;
    if (c >= C) return;
    float s = 0.f, q = 0.f;
    for (int m = 0; m < M; m++) {
        float v = X[(size_t)m * C + c];
        s += v;
        q = fmaf(v, v, q);
    }
    float mean = s / (float)M;
    float var = fmaxf(q / (float)M - mean * mean, 0.f);
    float inv = 1.f / sqrtf(var + BN_EPS);
    for (int m = 0; m < M; m++) {
        float v = (X[(size_t)m * C + c] - mean) * inv;
        if (relu) v = fmaxf(v, 0.f);
        X[(size_t)m * C + c] = v;
    }
}

// ---------------------------------------------------------------------------
// Max pool over group axis + BN(from raw sums) + ReLU  (gripper path only)
// ---------------------------------------------------------------------------
__global__ void maxpool_bn_kernel(const float* __restrict__ X, float* __restrict__ Y,
                                  int R, int ns, int C,
                                  const float* __restrict__ gsum,
                                  const float* __restrict__ gsq, float invM)
{
    unsigned total = (unsigned)R * C;
    unsigned stride = gridDim.x * blockDim.x;
    for (unsigned e = blockIdx.x * blockDim.x + threadIdx.x; e < total; e += stride) {
        int r = e / C;
        int c = e % C;
        const float* p = X + ((size_t)r * ns) * C + c;
        float m = -3.402823466e38f;
        for (int j = 0; j < ns; j++) m = fmaxf(m, p[(size_t)j * C]);
        float mean = gsum[c] * invM;
        float var = fmaxf(gsq[c] * invM - mean * mean, 0.f);
        float inv = 1.f / sqrtf(var + BN_EPS);
        Y[e] = fmaxf(0.f, (m - mean) * inv);
    }
}

// ---------------------------------------------------------------------------
// FPS1: one block per batch, 512 threads, padded to 20480 pts (40/thread).
// xy pairs in smem; z packed in regs; f32x2 distance math; pair-level argmax.
// ---------------------------------------------------------------------------
__global__ void __launch_bounds__(512) fps1_kernel(
    const float* __restrict__ xyz, int npoint,
    int* __restrict__ idx_out, float* __restrict__ newxyz)
{
    extern __shared__ float4 sxy[];   // [10240] pair -> (x0, x1, y0, y1)
    const int N = 20000;
    const int b = blockIdx.x;
    const int t = threadIdx.x;
    const float* P = xyz + (size_t)b * N * 3;

    __shared__ float s_v[16];
    __shared__ int   s_i[16];
    __shared__ float s_far[3];

    for (int i = t; i < 10240; i += 512) {
        int p0 = 2 * i, p1 = 2 * i + 1;
        float x0 = 0.f, y0 = 0.f, x1 = 0.f, y1 = 0.f;
        if (p0 < N) { x0 = P[p0 * 3]; y0 = P[p0 * 3 + 1]; }
        if (p1 < N) { x1 = P[p1 * 3]; y1 = P[p1 * 3 + 1]; }
        sxy[i] = make_float4(x0, x1, y0, y1);
    }
    unsigned long long zz[20];
    float dist[40];
#pragma unroll
    for (int k = 0; k < 20; k++) {
        int p0 = 2 * (t + k * 512), p1 = p0 + 1;
        float z0 = (p0 < N) ? P[p0 * 3 + 2] : 0.f;
        float z1 = (p1 < N) ? P[p1 * 3 + 2] : 0.f;
        PACK_F32X2(zz[k], __float_as_uint(z0), __float_as_uint(z1));
        dist[2 * k]     = (p0 < N) ? 1e10f : -1.f;
        dist[2 * k + 1] = (p1 < N) ? 1e10f : -1.f;
    }
    if (t == 0) {
        idx_out[b * npoint] = 0;
        float fx = P[0], fy = P[1], fz = P[2];
        newxyz[(size_t)b * npoint * 3 + 0] = fx;
        newxyz[(size_t)b * npoint * 3 + 1] = fy;
        newxyz[(size_t)b * npoint * 3 + 2] = fz;
        s_far[0] = fx; s_far[1] = fy; s_far[2] = fz;
    }
    __syncthreads();

    for (int it = 1; it < npoint; it++) {
        unsigned long long nfx2, nfy2, nfz2;
        {
            unsigned nx = __float_as_uint(-s_far[0]);
            unsigned ny = __float_as_uint(-s_far[1]);
            unsigned nz = __float_as_uint(-s_far[2]);
            PACK_F32X2(nfx2, nx, nx);
            PACK_F32X2(nfy2, ny, ny);
            PACK_F32X2(nfz2, nz, nz);
        }
        float best = -1.f;
        int bi = 0x7fffffff;
#pragma unroll
        for (int k = 0; k < 20; k++) {
            float4 q = sxy[t + k * 512];
            unsigned long long xx, yy;
            PACK_F32X2(xx, __float_as_uint(q.x), __float_as_uint(q.y));
            PACK_F32X2(yy, __float_as_uint(q.z), __float_as_uint(q.w));
            unsigned long long dx2, dy2, dz2, xs, ys, zs, s01, d2;
            ADD_F32X2(dx2, xx, nfx2);
            ADD_F32X2(dy2, yy, nfy2);
            ADD_F32X2(dz2, zz[k], nfz2);
            MUL_F32X2(xs, dx2, dx2);
            MUL_F32X2(ys, dy2, dy2);
            MUL_F32X2(zs, dz2, dz2);
            ADD_F32X2(s01, xs, ys);
            ADD_F32X2(d2, s01, zs);
            unsigned ulo, uhi;
            UNPACK_F32X2(ulo, uhi, d2);
            float n0 = fminf(dist[2 * k], __uint_as_float(ulo));
            dist[2 * k] = n0;
            float n1 = fminf(dist[2 * k + 1], __uint_as_float(uhi));
            dist[2 * k + 1] = n1;
            float pv = fmaxf(n0, n1);
            if (pv > best) {
                best = pv;
                bi = 2 * (t + k * 512) + ((n0 >= n1) ? 0 : 1);
            }
        }
#pragma unroll
        for (int o = 16; o > 0; o >>= 1) {
            float ov = __shfl_down_sync(0xffffffffu, best, o);
            int   oi = __shfl_down_sync(0xffffffffu, bi, o);
            if (ov > best || (ov == best && oi < bi)) { best = ov; bi = oi; }
        }
        if ((t & 31) == 0) { s_v[t >> 5] = best; s_i[t >> 5] = bi; }
        __syncthreads();
        if (t < 32) {
            best = (t < 16) ? s_v[t] : -1.f;
            bi   = (t < 16) ? s_i[t] : 0x7fffffff;
#pragma unroll
            for (int o = 8; o > 0; o >>= 1) {
                float ov = __shfl_down_sync(0xffffffffu, best, o);
                int   oi = __shfl_down_sync(0xffffffffu, bi, o);
                if (ov > best || (ov == best && oi < bi)) { best = ov; bi = oi; }
            }
            if (t == 0) {
                float4 q = sxy[bi >> 1];
                float fx2 = (bi & 1) ? q.y : q.x;
                float fy2 = (bi & 1) ? q.w : q.z;
                float fz2 = P[bi * 3 + 2];
                idx_out[b * npoint + it] = bi;
                newxyz[((size_t)b * npoint + it) * 3 + 0] = fx2;
                newxyz[((size_t)b * npoint + it) * 3 + 1] = fy2;
                newxyz[((size_t)b * npoint + it) * 3 + 2] = fz2;
                s_far[0] = fx2; s_far[1] = fy2; s_far[2] = fz2;
            }
        }
        __syncthreads();
    }
}

// ---------------------------------------------------------------------------
// FPS2: one warp per batch, all pts in registers (N=512), no block syncs.
// ---------------------------------------------------------------------------
__global__ void __launch_bounds__(32) fps_warp_kernel(
    const float* __restrict__ xyz, int N, int npoint,
    int* __restrict__ idx_out, float* __restrict__ newxyz)
{
    const int b = blockIdx.x;
    const int lane = threadIdx.x;
    const float* P = xyz + (size_t)b * N * 3;

    float x[16], y[16], z[16], dist[16];
#pragma unroll
    for (int k = 0; k < 16; k++) {
        int p = lane + k * 32;
        x[k] = P[p * 3 + 0];
        y[k] = P[p * 3 + 1];
        z[k] = P[p * 3 + 2];
        dist[k] = 1e10f;
    }
    float fx = P[0], fy = P[1], fz = P[2];
    if (lane == 0) {
        idx_out[b * npoint] = 0;
        newxyz[(size_t)b * npoint * 3 + 0] = fx;
        newxyz[(size_t)b * npoint * 3 + 1] = fy;
        newxyz[(size_t)b * npoint * 3 + 2] = fz;
    }
    for (int it = 1; it < npoint; it++) {
        float best = -1.f;
        int bi = 0x7fffffff;
#pragma unroll
        for (int k = 0; k < 16; k++) {
            float dx = __fsub_rn(x[k], fx);
            float dy = __fsub_rn(y[k], fy);
            float dz = __fsub_rn(z[k], fz);
            float d = __fadd_rn(__fadd_rn(__fmul_rn(dx, dx), __fmul_rn(dy, dy)),
                                __fmul_rn(dz, dz));
            float nd = fminf(dist[k], d);
            dist[k] = nd;
            if (nd > best) { best = nd; bi = lane + k * 32; }
        }
#pragma unroll
        for (int o = 16; o > 0; o >>= 1) {
            float ov = __shfl_xor_sync(0xffffffffu, best, o);
            int   oi = __shfl_xor_sync(0xffffffffu, bi, o);
            if (ov > best || (ov == best && oi < bi)) { best = ov; bi = oi; }
        }
        fx = P[bi * 3 + 0];
        fy = P[bi * 3 + 1];
        fz = P[bi * 3 + 2];
        if (lane == 0) {
            idx_out[b * npoint + it] = bi;
            newxyz[((size_t)b * npoint + it) * 3 + 0] = fx;
            newxyz[((size_t)b * npoint + it) * 3 + 1] = fy;
            newxyz[((size_t)b * npoint + it) * 3 + 2] = fz;
        }
    }
}

// ---------------------------------------------------------------------------
// Ball query — one warp per center; 512-point superchunks (48 loads in flight).
// ---------------------------------------------------------------------------
__global__ __launch_bounds__(256) void ballquery_kernel(
    const float* __restrict__ centers, const float* __restrict__ pts,
    int B, int S, int N, float r2, int nsample, int* __restrict__ out)
{
    int wg = (blockIdx.x * blockDim.x + threadIdx.x) >> 5;
    int lane = threadIdx.x & 31;
    if (wg >= B * S) return;
    int b = wg / S;
    const float* P = pts + (size_t)b * N * 3;
    float cx = centers[(size_t)wg * 3 + 0];
    float cy = centers[(size_t)wg * 3 + 1];
    float cz = centers[(size_t)wg * 3 + 2];
    int* o = out + (size_t)wg * nsample;

    int count = 0;
    int first = -1;
    for (int base = 0; base < N && count < nsample; base += 512) {
        bool ins[16];
#pragma unroll
        for (int j = 0; j < 16; j++) {
            int p = base + j * 32 + lane;
            bool inside = false;
            if (p < N) {
                float dx = __fsub_rn(cx, P[p * 3 + 0]);
                float dy = __fsub_rn(cy, P[p * 3 + 1]);
                float dz = __fsub_rn(cz, P[p * 3 + 2]);
                float d2 = __fadd_rn(__fadd_rn(__fmul_rn(dx, dx), __fmul_rn(dy, dy)),
                                     __fmul_rn(dz, dz));
                inside = d2 < r2;
            }
            ins[j] = inside;
        }
#pragma unroll
        for (int j = 0; j < 16; j++) {
            unsigned m = __ballot_sync(0xffffffffu, ins[j]);
            if (first < 0 && m) first = base + j * 32 + __ffs(m) - 1;
            if (ins[j]) {
                int pos = count + __popc(m & ((1u << lane) - 1u));
                if (pos < nsample) o[pos] = base + j * 32 + lane;
            }
            count += __popc(m);
        }
    }
    int start = count < nsample ? count : nsample;
    for (int k = start + lane; k < nsample; k += 32) o[k] = first;
}

// ---------------------------------------------------------------------------
// Concat kernels
// ---------------------------------------------------------------------------
__global__ void concat_sa3_kernel(const float* __restrict__ xyz2,
                                  const float* __restrict__ f2,
                                  float* __restrict__ out, int R, int CF)
{
    int C = 3 + CF;
    unsigned total = (unsigned)R * C;
    unsigned stride = gridDim.x * blockDim.x;
    for (unsigned e = blockIdx.x * blockDim.x + threadIdx.x; e < total; e += stride) {
        int r = e / C;
        int c = e % C;
        out[e] = (c < 3) ? xyz2[(size_t)r * 3 + c] : f2[(size_t)r * CF + (c - 3)];
    }
}

__global__ void concat_comb_kernel(const float* __restrict__ gf,
                                   const float* __restrict__ of,
                                   float* __restrict__ out, int B, int C1, int C2)
{
    int C = C1 + C2;
    unsigned total = (unsigned)B * C;
    unsigned stride = gridDim.x * blockDim.x;
    for (unsigned e = blockIdx.x * blockDim.x + threadIdx.x; e < total; e += stride) {
        int b = e / C;
        int c = e % C;
        out[e] = (c < C1) ? gf[(size_t)b * C1 + c] : of[(size_t)b * C2 + (c - C1)];
    }
}

// ---------------------------------------------------------------------------
// Host orchestration
// ---------------------------------------------------------------------------
static inline int cdiv(long a, long b) { return (int)((a + b - 1) / b); }
static int ew_blocks(long total)
{
    int b = cdiv(total, 256);
    return b > 4096 ? 4096 : b;
}

struct GatherArgs {
    const int* idx; const float* pts; const float* ctr; const float* feats;
    int npts, bShift, nsShift, cf; float rad;
};

static void launch_tile(const float* X, const float* W, float* Y,
                        int M, int N, int K,
                        const float* inSum, const float* inSq, float invMin,
                        float* outSum, float* outSq,
                        const GatherArgs* ga,
                        float* poolY = nullptr, int poolShift = 0)
{
    dim3 grid(cdiv(N, 64), cdiv(M, 128));
    if (ga) {
        gemm_tile_kernel<<<grid, 256>>>(X, W, Y, M, N, K,
            inSum, inSq, invMin, outSum, outSq,
            ga->idx, ga->pts, ga->ctr, ga->feats,
            ga->npts, ga->bShift, ga->nsShift, ga->cf, ga->rad,
            poolY, poolShift);
    } else {
        gemm_tile_kernel<<<grid, 256>>>(X, W, Y, M, N, K,
            inSum, inSq, invMin, outSum, outSq,
            nullptr, nullptr, nullptr, nullptr, 0, 0, 0, 0, 0.f,
            poolY, poolShift);
    }
}

extern "C" void kernel_launch(void* const* d_in, const int* in_sizes, int n_in,
                              void* d_out, int out_size)
{
    (void)in_sizes; (void)n_in; (void)out_size;
    const float* obj   = (const float*)d_in[0];
    const float* grip  = (const float*)d_in[1];
    const float* sa1w0 = (const float*)d_in[2];
    const float* sa1w1 = (const float*)d_in[3];
    const float* sa1w2 = (const float*)d_in[4];
    const float* sa2w0 = (const float*)d_in[5];
    const float* sa2w1 = (const float*)d_in[6];
    const float* sa2w2 = (const float*)d_in[7];
    const float* sa3w0 = (const float*)d_in[8];
    const float* sa3w1 = (const float*)d_in[9];
    const float* sa3w2 = (const float*)d_in[10];
    const float* gew0  = (const float*)d_in[11];
    const float* gew1  = (const float*)d_in[12];
    const float* gew2  = (const float*)d_in[13];
    const float* hw0   = (const float*)d_in[14];
    const float* hb0   = (const float*)d_in[15];
    const float* hw1   = (const float*)d_in[16];
    const float* hb1   = (const float*)d_in[17];
    const float* hw2   = (const float*)d_in[18];
    const float* hb2   = (const float*)d_in[19];

    float *bufA, *bufB, *praw, *f1, *f2, *sa3in, *gfeat, *objf, *comb, *h0, *h1;
    float *xyz1, *xyz2, *bsum, *bsq;
    int *fps1, *fps2, *bq1, *bq2;
    cudaGetSymbolAddress((void**)&bufA,  g_bufA);
    cudaGetSymbolAddress((void**)&bufB,  g_bufB);
    cudaGetSymbolAddress((void**)&praw,  g_praw);
    cudaGetSymbolAddress((void**)&f1,    g_f1);
    cudaGetSymbolAddress((void**)&f2,    g_f2);
    cudaGetSymbolAddress((void**)&sa3in, g_sa3in);
    cudaGetSymbolAddress((void**)&gfeat, g_gfeat);
    cudaGetSymbolAddress((void**)&objf,  g_objfeat);
    cudaGetSymbolAddress((void**)&comb,  g_comb);
    cudaGetSymbolAddress((void**)&h0,    g_h0);
    cudaGetSymbolAddress((void**)&h1,    g_h1);
    cudaGetSymbolAddress((void**)&xyz1,  g_xyz1);
    cudaGetSymbolAddress((void**)&xyz2,  g_xyz2);
    cudaGetSymbolAddress((void**)&fps1,  g_fps1);
    cudaGetSymbolAddress((void**)&fps2,  g_fps2);
    cudaGetSymbolAddress((void**)&bq1,   g_bq1);
    cudaGetSymbolAddress((void**)&bq2,   g_bq2);
    cudaGetSymbolAddress((void**)&bsum,  g_bnsum);
    cudaGetSymbolAddress((void**)&bsq,   g_bnsq);

    const int B = 8, N0 = 20000, G = 512;
    const int S1 = 512, NS1 = 32, S2 = 128, NS2 = 64;
    const float r2_1 = (float)(0.2 * 0.2);
    const float r2_2 = (float)(0.4 * 0.4);

    // per-layer stat region offsets (channels)
    const int oGE0 = 0, oGE1 = 64, oGE2 = 192;           // 64,128,128
    const int oS10 = 320, oS11 = 384, oS12 = 448;        // 64,64,128
    const int oS20 = 576, oS21 = 704, oS22 = 832;        // 128,128,256
    const int oS30 = 1088, oS31 = 1344, oS32 = 1856;     // 256,512,1024

    bn_zero_kernel<<<cdiv(4096, 256), 256>>>(bsum, bsq, 4096);

    // ---------------- FPS ----------------
    cudaFuncSetAttribute(fps1_kernel, cudaFuncAttributeMaxDynamicSharedMemorySize,
                         10240 * (int)sizeof(float4));
    fps1_kernel<<<B, 512, 10240 * sizeof(float4)>>>(obj, S1, fps1, xyz1);
    fps_warp_kernel<<<B, 32>>>(xyz1, S1, S2, fps2, xyz2);

    // ---------------- ball queries ----------------
    ballquery_kernel<<<cdiv((long)B * S1 * 32, 256), 256>>>(xyz1, obj, B, S1, N0,
                                                            r2_1, NS1, bq1);
    ballquery_kernel<<<cdiv((long)B * S2 * 32, 256), 256>>>(xyz2, xyz1, B, S2, S1,
                                                            r2_2, NS2, bq2);

    // ---------------- gripper encoder ----------------
    {
        int M = B * G;  // 4096
        float iM = 1.f / (float)M;
        launch_tile(grip, gew0, bufB, M, 64, 3,
                    nullptr, nullptr, 0.f, bsum + oGE0, bsq + oGE0, nullptr);
        launch_tile(bufB, gew1, bufA, M, 128, 64,
                    bsum + oGE0, bsq + oGE0, iM, bsum + oGE1, bsq + oGE1, nullptr);
        launch_tile(bufA, gew2, bufB, M, 128, 128,
                    bsum + oGE1, bsq + oGE1, iM, bsum + oGE2, bsq + oGE2, nullptr);
        maxpool_bn_kernel<<<ew_blocks((long)B * 128), 256>>>(bufB, gfeat, B, G, 128,
                                                             bsum + oGE2, bsq + oGE2, iM);
    }

    // ---------------- SA1 ----------------
    {
        int M = B * S1 * NS1;  // 131072
        float iM = 1.f / (float)M;
        GatherArgs ga = {bq1, obj, xyz1, nullptr, N0, 14, 5, 0, 0.2f};
        launch_tile(nullptr, sa1w0, bufB, M, 64, 3,
                    nullptr, nullptr, 0.f, bsum + oS10, bsq + oS10, &ga);
        launch_tile(bufB, sa1w1, bufA, M, 64, 64,
                    bsum + oS10, bsq + oS10, iM, bsum + oS11, bsq + oS11, nullptr);
        // layer 3: fused group-maxpool (ns=32 -> shift 5), no full store
        launch_tile(bufA, sa1w2, nullptr, M, 128, 64,
                    bsum + oS11, bsq + oS11, iM, bsum + oS12, bsq + oS12, nullptr,
                    praw, 5);
        poolnorm_kernel<<<ew_blocks((long)B * S1 * 128), 256>>>(
            praw, f1, (unsigned)(B * S1 * 128), 128, bsum + oS12, bsq + oS12, iM);
    }

    // ---------------- SA2 ----------------
    {
        int M = B * S2 * NS2;  // 65536
        float iM = 1.f / (float)M;
        GatherArgs ga = {bq2, xyz1, xyz2, f1, S1, 13, 6, 128, 0.4f};
        launch_tile(nullptr, sa2w0, bufB, M, 128, 131,
                    nullptr, nullptr, 0.f, bsum + oS20, bsq + oS20, &ga);
        launch_tile(bufB, sa2w1, bufA, M, 128, 128,
                    bsum + oS20, bsq + oS20, iM, bsum + oS21, bsq + oS21, nullptr);
        // layer 3: fused group-maxpool (ns=64 -> shift 6)
        launch_tile(bufA, sa2w2, nullptr, M, 256, 128,
                    bsum + oS21, bsq + oS21, iM, bsum + oS22, bsq + oS22, nullptr,
                    praw, 6);
        poolnorm_kernel<<<ew_blocks((long)B * S2 * 256), 256>>>(
            praw, f2, (unsigned)(B * S2 * 256), 256, bsum + oS22, bsq + oS22, iM);
    }

    // ---------------- SA3 (group_all) ----------------
    {
        int M = B * S2;  // 1024
        float iM = 1.f / (float)M;
        concat_sa3_kernel<<<ew_blocks((long)M * 259), 256>>>(xyz2, f2, sa3in, M, 256);
        launch_tile(sa3in, sa3w0, bufA, M, 256, 259,
                    nullptr, nullptr, 0.f, bsum + oS30, bsq + oS30, nullptr);
        launch_tile(bufA, sa3w1, bufB, M, 512, 256,
                    bsum + oS30, bsq + oS30, iM, bsum + oS31, bsq + oS31, nullptr);
        // layer 3: fused group-maxpool (ns=128 -> shift 7)
        launch_tile(bufB, sa3w2, nullptr, M, 1024, 512,
                    bsum + oS31, bsq + oS31, iM, bsum + oS32, bsq + oS32, nullptr,
                    praw, 7);
        poolnorm_kernel<<<ew_blocks((long)B * 1024), 256>>>(
            praw, objf, (unsigned)(B * 1024), 1024, bsum + oS32, bsq + oS32, iM);
    }

    // ---------------- head ----------------
    {
        concat_comb_kernel<<<ew_blocks((long)B * 1152), 256>>>(gfeat, objf, comb,
                                                               B, 128, 1024);
        bn_col_kernel<<<cdiv(1152, 256), 256>>>(comb, B, 1152, 0);
        gemm_small_kernel<<<cdiv(512, 8), 256>>>(comb, hw0, hb0, h0, B, 512, 1152, 0);
        bn_col_kernel<<<cdiv(512, 256), 256>>>(h0, B, 512, 1);
        gemm_small_kernel<<<cdiv(256, 8), 256>>>(h0, hw1, hb1, h1, B, 256, 512, 0);
        bn_col_kernel<<<cdiv(256, 256), 256>>>(h1, B, 256, 1);
        gemm_small_kernel<<<1, 256>>>(h1, hw2, hb2, (float*)d_out, B, 1, 256, 1);
    }
}